// round 11
// baseline (speedup 1.0000x reference)
#include <cuda_runtime.h>
#include <math.h>
#include <stdint.h>

#define NB 8
#define NTOK 1024
#define CC2 512
#define KVD 1792
#define NH 4
#define NMAPS (NB*NH)          // 32
#define MAPELEMS (CC2*KVD)     // 917504
#define NTILEMAP 64            // 16 x 4 stat tiles per map (BN=112 grid)
#define NPART (NMAPS*NTILEMAP)

// ---------------- scratch ----------------
__device__ __align__(128) float g_X   [NB*NTOK*KVD];
__device__ __align__(128) float g_cx2 [NB*NTOK*CC2];
__device__ __align__(128) float g_Gt  [NB*KVD*CC2];
__device__ __align__(128) float g_T   [NMAPS*CC2*KVD];
__device__ __align__(128) float g_S   [NMAPS*CC2*KVD];
__device__ __align__(128) float g_Mt  [NB*CC2*KVD];
__device__ __align__(128) float g_ctx [NB*NTOK*CC2];
__device__ __align__(128) float g_res [NB*NTOK*CC2];
__device__ __align__(128) float g_x2  [NB*NTOK*CC2];
__device__ __align__(128) float g_h1  [NB*NTOK*CC2*4];
__device__ __align__(128) float g_WqT [NH*CC2*CC2];
__device__ __align__(128) float g_WkT [NH*KVD*KVD];
__device__ __align__(128) float g_WoutT[CC2*CC2];
__device__ __align__(128) float g_fc1T[CC2*4*CC2];
__device__ __align__(128) float g_fc2T[CC2*CC2*4];
__device__ __align__(128) float g_part[NPART*2];

// ---------------- helpers ----------------
__device__ __forceinline__ uint32_t smem_u32(const void* p) {
    uint32_t a;
    asm("{ .reg .u64 t; cvta.to.shared.u64 t, %1; cvt.u32.u64 %0, t; }" : "=r"(a) : "l"(p));
    return a;
}
#define CP_ASYNC16(sa, ga) \
    asm volatile("cp.async.cg.shared.global [%0], [%1], 16;" :: "r"(sa), "l"(ga) : "memory")
#define CP_COMMIT() asm volatile("cp.async.commit_group;" ::: "memory")
#define CP_WAIT2()  asm volatile("cp.async.wait_group 2;" ::: "memory")

__device__ __forceinline__ void mma_tf32(float* c, const uint32_t* a, const uint32_t* b) {
    asm volatile(
        "mma.sync.aligned.m16n8k8.row.col.f32.tf32.tf32.f32 "
        "{%0,%1,%2,%3}, {%4,%5,%6,%7}, {%8,%9}, {%0,%1,%2,%3};"
        : "+f"(c[0]), "+f"(c[1]), "+f"(c[2]), "+f"(c[3])
        : "r"(a[0]), "r"(a[1]), "r"(a[2]), "r"(a[3]), "r"(b[0]), "r"(b[1]));
}

// ---------------- tensor-core GEMM: D = alpha * sum_seg A[M,K] @ B[N,K]^T --
// CTA tile 128 x (16*NI); 4 warps 2x2; warp tile 64 x (8*NI). NI = 8 or 7.
#define BM 128
#define PAD 36
#define SM_BUF (128*PAD)
#define NSTAGE 3
#define SM_TOTAL (NSTAGE*2*SM_BUF*4)  // 110592 bytes

struct TCP {
    const float *A, *B; float *C;
    int lda, ldb, ldc, K;
    long sA, sB, sC;
    int aSel, bSel, nseg;
    long segA, segB;
    float alpha;
    const float* bias;
    const float* add; int ldAdd; long sAdd;
    float* part;
};

// EPI: 0 plain; 1 bias+gelu; 2 (+bias)+add; 3 plain + per-CTA IN partial stats
template <int EPI, int NI>
__global__ void __launch_bounds__(128, 2) gemm_mma(TCP p)
{
    extern __shared__ float sm[];
    uint32_t sb = smem_u32(sm);
    const int BN = NI * 16;

    int t = threadIdx.x, lane = t & 31, w = t >> 5;
    int z = blockIdx.z;
    int m0 = blockIdx.y * BM, n0 = blockIdx.x * BN;
    int az = p.aSel == 0 ? z : (p.aSel == 1 ? (z & 3) : (z >> 2));
    int bz = p.bSel == 0 ? z : (p.bSel == 1 ? (z & 3) : (z >> 2));
    const float* Ab = p.A + (long)az * p.sA + (size_t)m0 * p.lda;
    const float* Bb = p.B + (long)bz * p.sB + (size_t)n0 * p.ldb;
    float* Cz = p.C + (long)z * p.sC;

    int kIters = p.K >> 5;
    int nIt = kIters * p.nseg;
    int seg = 0, kk = 0;

    auto issue = [&](int buf) {
        const float* Ag = Ab + (long)seg * p.segA + kk;
        const float* Bg = Bb + (long)seg * p.segB + kk;
        uint32_t da = sb + (2 * buf) * SM_BUF * 4;
        uint32_t db = sb + (2 * buf + 1) * SM_BUF * 4;
        #pragma unroll
        for (int i = 0; i < 8; i++) {
            int task = t + i * 128, row = task >> 3, q = task & 7;
            CP_ASYNC16(da + (row * PAD + q * 4) * 4, Ag + (size_t)row * p.lda + q * 4);
        }
        #pragma unroll
        for (int i = 0; i < NI; i++) {
            int task = t + i * 128, row = task >> 3, q = task & 7;
            CP_ASYNC16(db + (row * PAD + q * 4) * 4, Bg + (size_t)row * p.ldb + q * 4);
        }
        CP_COMMIT();
        kk += 32; if (kk == p.K) { kk = 0; seg++; }
    };

    issue(0);
    if (nIt > 1) issue(1);

    int wm = (w >> 1) * 64, wn = (w & 1) * (NI * 8);
    float acc[4][NI][4] = {};
    int arowL = wm + (lane >> 2), browL = wn + (lane >> 2);

    for (int it = 0; it < nIt; it++) {
        int buf = it % NSTAGE;
        if (it + 2 < nIt) issue((it + 2) % NSTAGE);
        else CP_COMMIT();
        CP_WAIT2();
        __syncthreads();

        const uint32_t* Ai = (const uint32_t*)(sm + (2 * buf) * SM_BUF);
        const uint32_t* Bi = (const uint32_t*)(sm + (2 * buf + 1) * SM_BUF);
        #pragma unroll
        for (int ks = 0; ks < 4; ks++) {
            int ac = ks * 8 + (lane & 3);
            uint32_t a[4][4], b[NI][2];
            #pragma unroll
            for (int mi = 0; mi < 4; mi++) {
                const uint32_t* p0 = Ai + (size_t)(arowL + mi * 16) * PAD + ac;
                a[mi][0] = p0[0];
                a[mi][2] = p0[4];
                a[mi][1] = p0[8 * PAD];
                a[mi][3] = p0[8 * PAD + 4];
            }
            #pragma unroll
            for (int ni = 0; ni < NI; ni++) {
                const uint32_t* p0 = Bi + (size_t)(browL + ni * 8) * PAD + ac;
                b[ni][0] = p0[0];
                b[ni][1] = p0[4];
            }
            #pragma unroll
            for (int mi = 0; mi < 4; mi++)
                #pragma unroll
                for (int ni = 0; ni < NI; ni++)
                    mma_tf32(acc[mi][ni], a[mi], b[ni]);
        }
        __syncthreads();
    }

    // -------- epilogue --------
    float psum = 0.f, psq = 0.f;
    #pragma unroll
    for (int mi = 0; mi < 4; mi++) {
        #pragma unroll
        for (int ni = 0; ni < NI; ni++) {
            int r0 = m0 + wm + mi * 16 + (lane >> 2);
            int cc = n0 + wn + ni * 8 + (lane & 3) * 2;
            #pragma unroll
            for (int h = 0; h < 2; h++) {
                int gr = r0 + h * 8;
                float v0 = p.alpha * acc[mi][ni][h * 2 + 0];
                float v1 = p.alpha * acc[mi][ni][h * 2 + 1];
                if (EPI == 1) {
                    v0 += p.bias[cc]; v1 += p.bias[cc + 1];
                    v0 = 0.5f * v0 * (1.f + erff(v0 * 0.70710678118654752f));
                    v1 = 0.5f * v1 * (1.f + erff(v1 * 0.70710678118654752f));
                }
                if (EPI == 2) {
                    if (p.bias) { v0 += p.bias[cc]; v1 += p.bias[cc + 1]; }
                    const float* ap = p.add + (long)z * p.sAdd + (size_t)gr * p.ldAdd + cc;
                    float2 av = *(const float2*)ap;
                    v0 += av.x; v1 += av.y;
                }
                if (EPI == 3) { psum += v0 + v1; psq += v0 * v0 + v1 * v1; }
                *(float2*)&Cz[(size_t)gr * p.ldc + cc] = make_float2(v0, v1);
            }
        }
    }
    if (EPI == 3) {
        #pragma unroll
        for (int o = 16; o > 0; o >>= 1) {
            psum += __shfl_down_sync(0xffffffffu, psum, o);
            psq  += __shfl_down_sync(0xffffffffu, psq,  o);
        }
        __syncthreads();
        if (lane == 0) { sm[w] = psum; sm[8 + w] = psq; }
        __syncthreads();
        if (t == 0) {
            float s = 0.f, ss = 0.f;
            #pragma unroll
            for (int i = 0; i < 4; i++) { s += sm[i]; ss += sm[8 + i]; }
            int idx = (z * 4 + blockIdx.y) * gridDim.x + blockIdx.x;
            p.part[idx * 2] = s;
            p.part[idx * 2 + 1] = ss;
        }
    }
}

// ---------------- TN GEMM (R10 winner, unchanged) --------------------------
#define PADK 132
#define SM_BUF_TN (32*PADK)
#define SM_TOTAL_TN (NSTAGE*2*SM_BUF_TN*4)

__global__ void __launch_bounds__(128, 2) gemm_mma_tn(TCP p)
{
    extern __shared__ float sm[];
    uint32_t sb = smem_u32(sm);

    int t = threadIdx.x, lane = t & 31, w = t >> 5;
    int z = blockIdx.z;
    int m0 = blockIdx.y * BM, n0 = blockIdx.x * 128;
    const float* Ab = p.A + (long)z * p.sA + m0;
    const float* Bb = p.B + (long)z * p.sB + n0;
    float* Cz = p.C + (long)z * p.sC;

    int nIt = p.K >> 5;
    int kk = 0;

    auto issue = [&](int buf) {
        const float* Ag = Ab + (size_t)kk * p.lda;
        const float* Bg = Bb + (size_t)kk * p.ldb;
        uint32_t da = sb + (2 * buf) * SM_BUF_TN * 4;
        uint32_t db = sb + (2 * buf + 1) * SM_BUF_TN * 4;
        #pragma unroll
        for (int i = 0; i < 8; i++) {
            int task = t + i * 128, kr = task >> 5, q = task & 31;
            CP_ASYNC16(da + (kr * PADK + q * 4) * 4, Ag + (size_t)kr * p.lda + q * 4);
            CP_ASYNC16(db + (kr * PADK + q * 4) * 4, Bg + (size_t)kr * p.ldb + q * 4);
        }
        CP_COMMIT();
        kk += 32;
    };

    issue(0);
    if (nIt > 1) issue(1);

    int wm = (w >> 1) * 64, wn = (w & 1) * 64;
    float acc[4][8][4] = {};
    int arowL = wm + (lane >> 2), browL = wn + (lane >> 2);

    for (int it = 0; it < nIt; it++) {
        int buf = it % NSTAGE;
        if (it + 2 < nIt) issue((it + 2) % NSTAGE);
        else CP_COMMIT();
        CP_WAIT2();
        __syncthreads();

        const uint32_t* Ai = (const uint32_t*)(sm + (2 * buf) * SM_BUF_TN);
        const uint32_t* Bi = (const uint32_t*)(sm + (2 * buf + 1) * SM_BUF_TN);
        #pragma unroll
        for (int ks = 0; ks < 4; ks++) {
            int ac = ks * 8 + (lane & 3);
            uint32_t a[4][4], b[8][2];
            #pragma unroll
            for (int mi = 0; mi < 4; mi++) {
                const uint32_t* p0 = Ai + (size_t)ac * PADK + arowL + mi * 16;
                a[mi][0] = p0[0];
                a[mi][1] = p0[8];
                a[mi][2] = p0[4 * PADK];
                a[mi][3] = p0[4 * PADK + 8];
            }
            #pragma unroll
            for (int ni = 0; ni < 8; ni++) {
                const uint32_t* p0 = Bi + (size_t)ac * PADK + browL + ni * 8;
                b[ni][0] = p0[0];
                b[ni][1] = p0[4 * PADK];
            }
            #pragma unroll
            for (int mi = 0; mi < 4; mi++)
                #pragma unroll
                for (int ni = 0; ni < 8; ni++)
                    mma_tf32(acc[mi][ni], a[mi], b[ni]);
        }
        __syncthreads();
    }

    #pragma unroll
    for (int mi = 0; mi < 4; mi++) {
        #pragma unroll
        for (int ni = 0; ni < 8; ni++) {
            int r0 = m0 + wm + mi * 16 + (lane >> 2);
            int cc = n0 + wn + ni * 8 + (lane & 3) * 2;
            #pragma unroll
            for (int h = 0; h < 2; h++) {
                int gr = r0 + h * 8;
                *(float2*)&Cz[(size_t)gr * p.ldc + cc] =
                    make_float2(acc[mi][ni][h * 2 + 0], acc[mi][ni][h * 2 + 1]);
            }
        }
    }
}

// ---------------- transpose ----------------
__global__ void __launch_bounds__(256) transpose_kernel(
    const float* __restrict__ in, float* __restrict__ out, int rows, int cols)
{
    __shared__ float tile[32][33];
    long zo = (long)blockIdx.z * rows * cols;
    const float* ip = in + zo;
    float* op = out + zo;
    int c0 = blockIdx.x * 32, r0 = blockIdx.y * 32;
    int tx = threadIdx.x & 31, ty = threadIdx.x >> 5;
    #pragma unroll
    for (int i = 0; i < 4; i++)
        tile[ty + i * 8][tx] = ip[(size_t)(r0 + ty + i * 8) * cols + c0 + tx];
    __syncthreads();
    #pragma unroll
    for (int i = 0; i < 4; i++)
        op[(size_t)(c0 + ty + i * 8) * rows + r0 + tx] = tile[tx][ty + i * 8];
}

// ---------------- elementwise ----------------
__device__ __forceinline__ float blockReduceSum(float v, float* sbuf) {
    #pragma unroll
    for (int o = 16; o > 0; o >>= 1) v += __shfl_down_sync(0xffffffffu, v, o);
    int lane = threadIdx.x & 31, w = threadIdx.x >> 5;
    if (lane == 0) sbuf[w] = v;
    __syncthreads();
    float tot = 0.f;
    #pragma unroll
    for (int i = 0; i < 8; i++) tot += sbuf[i];
    __syncthreads();
    return tot;
}

__global__ void __launch_bounds__(256) ln_all_kernel(
    const float* __restrict__ e1, const float* __restrict__ e2, const float* __restrict__ e3,
    const float* __restrict__ g1, const float* __restrict__ b1,
    const float* __restrict__ ga, const float* __restrict__ ba,
    float* __restrict__ X, float* __restrict__ cx2)
{
    __shared__ float xs[KVD];
    __shared__ float red[8];
    int tok = blockIdx.x, t = threadIdx.x;
    const float* p1 = e1 + (size_t)tok * 256;
    const float* p2 = e2 + (size_t)tok * 512;
    const float* p3 = e3 + (size_t)tok * 1024;
    xs[t] = p1[t];
    xs[256 + t] = p2[t];
    xs[512 + t] = p2[256 + t];
    #pragma unroll
    for (int i = 0; i < 4; i++) xs[768 + t + i * 256] = p3[t + i * 256];
    __syncthreads();
    float s = 0.f, ss = 0.f, s2 = 0.f, ss2 = 0.f;
    for (int i = t; i < KVD; i += 256) { float x = xs[i]; s += x; ss += x * x; }
    for (int i = t; i < 512; i += 256) { float x = xs[256 + i]; s2 += x; ss2 += x * x; }
    s  = blockReduceSum(s,  red);
    ss = blockReduceSum(ss, red);
    s2 = blockReduceSum(s2, red);
    ss2= blockReduceSum(ss2,red);
    float m  = s * (1.f / KVD), r = rsqrtf(ss * (1.f / KVD) - m * m + 1e-6f);
    float m2 = s2 * (1.f / 512.f), r2 = rsqrtf(ss2 * (1.f / 512.f) - m2 * m2 + 1e-6f);
    float* Xo = X + (size_t)tok * KVD;
    float* co = cx2 + (size_t)tok * 512;
    for (int i = t; i < KVD; i += 256) Xo[i] = (xs[i] - m) * r * ga[i] + ba[i];
    for (int i = t; i < 512; i += 256) co[i] = (xs[256 + i] - m2) * r2 * g1[i] + b1[i];
}

__global__ void __launch_bounds__(256) ln512_kernel(
    const float* __restrict__ in, const float* __restrict__ g, const float* __restrict__ b,
    float* __restrict__ out)
{
    __shared__ float red[8];
    int tok = blockIdx.x, t = threadIdx.x;
    const float* p = in + (size_t)tok * 512;
    float x0 = p[t], x1 = p[t + 256];
    float s = blockReduceSum(x0 + x1, red);
    float ss = blockReduceSum(x0 * x0 + x1 * x1, red);
    float m = s * (1.f / 512.f);
    float r = rsqrtf(ss * (1.f / 512.f) - m * m + 1e-6f);
    float* o = out + (size_t)tok * 512;
    o[t] = (x0 - m) * r * g[t] + b[t];
    o[t + 256] = (x1 - m) * r * g[t + 256] + b[t + 256];
}

__global__ void __launch_bounds__(256) softmax_kernel(float* __restrict__ S,
                                                      const float* __restrict__ part)
{
    __shared__ float red[8];
    int row = blockIdx.x, t = threadIdx.x;
    int map = row >> 9;
    float s0 = 0.f, q0 = 0.f;
    const float2* pp = (const float2*)part + map * NTILEMAP;
    #pragma unroll 8
    for (int i = 0; i < NTILEMAP; i++) { float2 v = pp[i]; s0 += v.x; q0 += v.y; }
    float invn = 1.f / (float)MAPELEMS;
    float mean = s0 * invn;
    float r = rsqrtf(q0 * invn - mean * mean + 1e-5f);

    float* p = S + (size_t)row * KVD;
    float v[7];
    float mx = -1e30f;
    #pragma unroll
    for (int j = 0; j < 7; j++) { v[j] = p[t + j * 256] * r; mx = fmaxf(mx, v[j]); }
    #pragma unroll
    for (int o = 16; o > 0; o >>= 1) mx = fmaxf(mx, __shfl_xor_sync(0xffffffffu, mx, o));
    int lane = t & 31, w = t >> 5;
    if (lane == 0) red[w] = mx;
    __syncthreads();
    float bm = red[0];
    #pragma unroll
    for (int i = 1; i < 8; i++) bm = fmaxf(bm, red[i]);
    __syncthreads();
    float s = 0.f;
    #pragma unroll
    for (int j = 0; j < 7; j++) { v[j] = expf(v[j] - bm); s += v[j]; }
    s = blockReduceSum(s, red);
    float inv = 1.f / s;
    #pragma unroll
    for (int j = 0; j < 7; j++) p[t + j * 256] = v[j] * inv;
}

// ---------------- host ----------------
static inline TCP mkP(const float* A, const float* B, float* C,
                      int lda, int ldb, int ldc, int K,
                      long sA, long sB, long sC, int aSel, int bSel,
                      int nseg, long segA, long segB, float alpha,
                      const float* bias, const float* add, int ldAdd, long sAdd,
                      float* part = nullptr)
{
    TCP p; p.A = A; p.B = B; p.C = C; p.lda = lda; p.ldb = ldb; p.ldc = ldc; p.K = K;
    p.sA = sA; p.sB = sB; p.sC = sC; p.aSel = aSel; p.bSel = bSel;
    p.nseg = nseg; p.segA = segA; p.segB = segB; p.alpha = alpha;
    p.bias = bias; p.add = add; p.ldAdd = ldAdd; p.sAdd = sAdd; p.part = part;
    return p;
}

extern "C" void kernel_launch(void* const* d_in, const int* in_sizes, int n_in,
                              void* d_out, int out_size)
{
    const float* emb1   = (const float*)d_in[0];
    const float* emb2   = (const float*)d_in[1];
    const float* emb3   = (const float*)d_in[2];
    const float* Wq     = (const float*)d_in[3];
    const float* Wk     = (const float*)d_in[4];
    const float* Wv     = (const float*)d_in[5];
    const float* Wout   = (const float*)d_in[6];
    const float* ln1_g  = (const float*)d_in[7];
    const float* ln1_b  = (const float*)d_in[8];
    const float* lnall_g= (const float*)d_in[9];
    const float* lnall_b= (const float*)d_in[10];
    const float* lnffn_g= (const float*)d_in[11];
    const float* lnffn_b= (const float*)d_in[12];
    const float* fc1_w  = (const float*)d_in[13];
    const float* fc1_b  = (const float*)d_in[14];
    const float* fc2_w  = (const float*)d_in[15];
    const float* fc2_b  = (const float*)d_in[16];
    float* out = (float*)d_out;

    cudaFuncSetAttribute(gemm_mma<0,8>, cudaFuncAttributeMaxDynamicSharedMemorySize, SM_TOTAL);
    cudaFuncSetAttribute(gemm_mma<1,8>, cudaFuncAttributeMaxDynamicSharedMemorySize, SM_TOTAL);
    cudaFuncSetAttribute(gemm_mma<2,8>, cudaFuncAttributeMaxDynamicSharedMemorySize, SM_TOTAL);
    cudaFuncSetAttribute(gemm_mma<0,7>, cudaFuncAttributeMaxDynamicSharedMemorySize, SM_TOTAL);
    cudaFuncSetAttribute(gemm_mma<3,7>, cudaFuncAttributeMaxDynamicSharedMemorySize, SM_TOTAL);
    cudaFuncSetAttribute(gemm_mma_tn, cudaFuncAttributeMaxDynamicSharedMemorySize, SM_TOTAL_TN);

    float *X,*cx2,*Gt,*T,*S,*Mt,*ctx,*res,*x2,*h1;
    float *WqT,*WkT,*WoutT,*fc1T,*fc2T,*part;
    cudaGetSymbolAddress((void**)&X,    g_X);
    cudaGetSymbolAddress((void**)&cx2,  g_cx2);
    cudaGetSymbolAddress((void**)&Gt,   g_Gt);
    cudaGetSymbolAddress((void**)&T,    g_T);
    cudaGetSymbolAddress((void**)&S,    g_S);
    cudaGetSymbolAddress((void**)&Mt,   g_Mt);
    cudaGetSymbolAddress((void**)&ctx,  g_ctx);
    cudaGetSymbolAddress((void**)&res,  g_res);
    cudaGetSymbolAddress((void**)&x2,   g_x2);
    cudaGetSymbolAddress((void**)&h1,   g_h1);
    cudaGetSymbolAddress((void**)&WqT,  g_WqT);
    cudaGetSymbolAddress((void**)&WkT,  g_WkT);
    cudaGetSymbolAddress((void**)&WoutT,g_WoutT);
    cudaGetSymbolAddress((void**)&fc1T, g_fc1T);
    cudaGetSymbolAddress((void**)&fc2T, g_fc2T);
    cudaGetSymbolAddress((void**)&part, g_part);

    const long MAPSZ = (long)CC2 * KVD;
    const float inv_sqrt_kv = 1.f / sqrtf((float)KVD);

    // weight transposes
    transpose_kernel<<<dim3(16,16,4), 256>>>(Wq, WqT, 512, 512);
    transpose_kernel<<<dim3(56,56,4), 256>>>(Wk, WkT, KVD, KVD);
    transpose_kernel<<<dim3(16,16,1), 256>>>(Wout, WoutT, 512, 512);
    transpose_kernel<<<dim3(64,16,1), 256>>>(fc1_w, fc1T, 512, 2048);
    transpose_kernel<<<dim3(16,64,1), 256>>>(fc2_w, fc2T, 2048, 512);

    // 1. LayerNorms
    ln_all_kernel<<<NB*NTOK, 256>>>(emb1, emb2, emb3, ln1_g, ln1_b,
                                    lnall_g, lnall_b, X, cx2);

    // 2. Gt[b][j][c] : TN form, M=KVD, N=512, K=1024
    gemm_mma_tn<<<dim3(4,14,8), 128, SM_TOTAL_TN>>>(
        mkP(X, cx2, Gt, KVD, 512, 512, NTOK,
            (long)NTOK*KVD, (long)NTOK*512, (long)KVD*512, 0, 0,
            1, 0, 0, 1.f, nullptr, nullptr, 0, 0));

    // 3. T[z][d][j] : M=512, N=KVD, K=512 ; BN=112 grid (16,4,32) -> 99% wave eff
    gemm_mma<0,7><<<dim3(16,4,32), 128, SM_TOTAL>>>(
        mkP(WqT, Gt, T, 512, 512, KVD, 512,
            (long)512*512, (long)KVD*512, MAPSZ, 1, 2,
            1, 0, 0, 1.f, nullptr, nullptr, 0, 0));

    // 4. S[z][d][k'] : M=512, N=KVD, K=KVD ; BN=112 + fused IN partial stats
    gemm_mma<3,7><<<dim3(16,4,32), 128, SM_TOTAL>>>(
        mkP(T, WkT, S, KVD, KVD, KVD, KVD,
            MAPSZ, (long)KVD*KVD, MAPSZ, 0, 1,
            1, 0, 0, inv_sqrt_kv, nullptr, nullptr, 0, 0, part));

    // 5. probs = softmax(rstd * S)
    softmax_kernel<<<NMAPS*512, 256>>>(S, part);

    // 6. Mt[b][c][j] : M=512, N=KVD, 4 segs ; BN=112 grid (16,4,8)
    gemm_mma<0,7><<<dim3(16,4,8), 128, SM_TOTAL>>>(
        mkP(S, Wv, Mt, KVD, KVD, KVD, KVD,
            4*MAPSZ, 0, (long)512*KVD, 0, 0,
            4, MAPSZ, (long)KVD*KVD, 0.25f, nullptr, nullptr, 0, 0));

    // 7. ctx[b][t][c] : M=1024, N=512, K=KVD
    gemm_mma<0,8><<<dim3(4,8,8), 128, SM_TOTAL>>>(
        mkP(X, Mt, ctx, KVD, KVD, 512, KVD,
            (long)NTOK*KVD, (long)512*KVD, (long)NTOK*512, 0, 0,
            1, 0, 0, 1.f, nullptr, nullptr, 0, 0));

    // 8. res = ctx @ Wout + emb2 : M=8192, N=512, K=512
    gemm_mma<2,8><<<dim3(4,64,1), 128, SM_TOTAL>>>(
        mkP(ctx, WoutT, res, 512, 512, 512, 512,
            0, 0, 0, 0, 0, 1, 0, 0, 1.f, nullptr, emb2, 512, 0));

    // 9. x2 = LN(res)
    ln512_kernel<<<NB*NTOK, 256>>>(res, lnffn_g, lnffn_b, x2);

    // 10. h1 = gelu(x2 @ fc1 + b1) : M=8192, N=2048, K=512
    gemm_mma<1,8><<<dim3(16,64,1), 128, SM_TOTAL>>>(
        mkP(x2, fc1T, h1, 512, 512, 2048, 512,
            0, 0, 0, 0, 0, 1, 0, 0, 1.f, fc1_b, nullptr, 0, 0));

    // 11. out = h1 @ fc2 + b2 + res : M=8192, N=512, K=2048
    gemm_mma<2,8><<<dim3(4,64,1), 128, SM_TOTAL>>>(
        mkP(h1, fc2T, out, 2048, 2048, 512, 2048,
            0, 0, 0, 0, 0, 1, 0, 0, 1.f, fc2_b, res, 512, 0));
}

// round 13
// speedup vs baseline: 1.6028x; 1.6028x over previous
#include <cuda_runtime.h>
#include <cuda_fp16.h>
#include <math.h>
#include <stdint.h>

#define NB 8
#define NTOK 1024
#define CC2 512
#define KVD 1792
#define NH 4
#define NMAPS (NB*NH)          // 32
#define MAPELEMS (CC2*KVD)     // 917504
#define NTILEMAP 56            // 14 x 4 stat tiles per map
#define NPART (NMAPS*NTILEMAP)

// ---------------- scratch ----------------
__device__ __align__(128) float  g_X   [NB*NTOK*KVD];     // fp32 (TN Gt)
__device__ __align__(128) __half g_Xh  [NB*NTOK*KVD];     // half (ctx GEMM)
__device__ __align__(128) float  g_cx2 [NB*NTOK*CC2];     // fp32 (TN Gt)
__device__ __align__(128) __half g_Gt  [NB*KVD*CC2];
__device__ __align__(128) __half g_T   [NMAPS*CC2*KVD];
__device__ __align__(128) __half g_S   [NMAPS*CC2*KVD];
__device__ __align__(128) __half g_Mt  [NB*CC2*KVD];
__device__ __align__(128) __half g_ctx [NB*NTOK*CC2];
__device__ __align__(128) float  g_res [NB*NTOK*CC2];
__device__ __align__(128) __half g_x2  [NB*NTOK*CC2];
__device__ __align__(128) __half g_h1  [NB*NTOK*CC2*4];
__device__ __align__(128) __half g_WqT [NH*CC2*CC2];
__device__ __align__(128) __half g_WkT [NH*KVD*KVD];
__device__ __align__(128) __half g_WoutT[CC2*CC2];
__device__ __align__(128) __half g_fc1T[CC2*4*CC2];
__device__ __align__(128) __half g_fc2T[CC2*CC2*4];
__device__ __align__(128) __half g_Wvh [NH*KVD*KVD];
__device__ __align__(128) float  g_part[NPART*2];

// ---------------- helpers ----------------
__device__ __forceinline__ uint32_t smem_u32(const void* p) {
    uint32_t a;
    asm("{ .reg .u64 t; cvta.to.shared.u64 t, %1; cvt.u32.u64 %0, t; }" : "=r"(a) : "l"(p));
    return a;
}
#define CP_ASYNC16(sa, ga) \
    asm volatile("cp.async.cg.shared.global [%0], [%1], 16;" :: "r"(sa), "l"(ga) : "memory")
#define CP_COMMIT() asm volatile("cp.async.commit_group;" ::: "memory")
#define CP_WAIT2()  asm volatile("cp.async.wait_group 2;" ::: "memory")

__device__ __forceinline__ void mma_f16(float* c, const uint32_t* a, const uint32_t* b) {
    asm volatile(
        "mma.sync.aligned.m16n8k16.row.col.f32.f16.f16.f32 "
        "{%0,%1,%2,%3}, {%4,%5,%6,%7}, {%8,%9}, {%0,%1,%2,%3};"
        : "+f"(c[0]), "+f"(c[1]), "+f"(c[2]), "+f"(c[3])
        : "r"(a[0]), "r"(a[1]), "r"(a[2]), "r"(a[3]), "r"(b[0]), "r"(b[1]));
}
__device__ __forceinline__ void mma_tf32(float* c, const uint32_t* a, const uint32_t* b) {
    asm volatile(
        "mma.sync.aligned.m16n8k8.row.col.f32.tf32.tf32.f32 "
        "{%0,%1,%2,%3}, {%4,%5,%6,%7}, {%8,%9}, {%0,%1,%2,%3};"
        : "+f"(c[0]), "+f"(c[1]), "+f"(c[2]), "+f"(c[3])
        : "r"(a[0]), "r"(a[1]), "r"(a[2]), "r"(a[3]), "r"(b[0]), "r"(b[1]));
}

// ---------------- fp16 tensor-core GEMM: D = alpha*sum_seg A[M,K]@B[N,K]^T --
// CTA 128x128, 4 warps 2x2, warp tile 64x64. K-chunk 32 halves (2 k16 steps).
#define BM 128
#define PADH 40                       // halves per smem row (20 words)
#define PADW 20
#define SM_BUF_H (128*PADH)           // halves per operand buffer (5120)
#define NSTAGE 3
#define SM_TOTAL_H (NSTAGE*2*SM_BUF_H*2)   // 61440 bytes

struct TCP {
    const void *A, *B; void *C;
    int lda, ldb, ldc, K;
    long sA, sB, sC;
    int aSel, bSel, nseg;
    long segA, segB;
    float alpha;
    const float* bias;
    const float* add; int ldAdd; long sAdd;
    float* part;
};

// EPI: 0 plain; 1 bias+gelu; 2 (+bias)+add; 3 plain + IN partial stats
// OUTH: 1 = half2 store, 0 = float2 store
template <int EPI, int OUTH>
__global__ void __launch_bounds__(128, 2) gemm_mma(TCP p)
{
    extern __shared__ float smf[];
    __half* sm = (__half*)smf;
    uint32_t sb = smem_u32(sm);

    int t = threadIdx.x, lane = t & 31, w = t >> 5;
    int z = blockIdx.z;
    int m0 = blockIdx.y * BM, n0 = blockIdx.x * 128;
    int az = p.aSel == 0 ? z : (p.aSel == 1 ? (z & 3) : (z >> 2));
    int bz = p.bSel == 0 ? z : (p.bSel == 1 ? (z & 3) : (z >> 2));
    const __half* Ab = (const __half*)p.A + (long)az * p.sA + (size_t)m0 * p.lda;
    const __half* Bb = (const __half*)p.B + (long)bz * p.sB + (size_t)n0 * p.ldb;

    int kIters = p.K >> 5;
    int nIt = kIters * p.nseg;
    int seg = 0, kk = 0;

    auto issue = [&](int buf) {
        const __half* Ag = Ab + (long)seg * p.segA + kk;
        const __half* Bg = Bb + (long)seg * p.segB + kk;
        uint32_t da = sb + (2 * buf) * SM_BUF_H * 2;
        uint32_t db = sb + (2 * buf + 1) * SM_BUF_H * 2;
        #pragma unroll
        for (int i = 0; i < 4; i++) {
            int task = t + i * 128, row = task >> 2, q = task & 3;
            CP_ASYNC16(da + row * (PADH * 2) + q * 16, Ag + (size_t)row * p.lda + q * 8);
            CP_ASYNC16(db + row * (PADH * 2) + q * 16, Bg + (size_t)row * p.ldb + q * 8);
        }
        CP_COMMIT();
        kk += 32; if (kk == p.K) { kk = 0; seg++; }
    };

    issue(0);
    if (nIt > 1) issue(1);

    int wm = (w >> 1) * 64, wn = (w & 1) * 64;
    float acc[4][8][4] = {};
    int arowL = wm + (lane >> 2), browL = wn + (lane >> 2);

    for (int it = 0; it < nIt; it++) {
        int buf = it % NSTAGE;
        if (it + 2 < nIt) issue((it + 2) % NSTAGE);
        else CP_COMMIT();
        CP_WAIT2();
        __syncthreads();

        const uint32_t* Ai = (const uint32_t*)(sm + (2 * buf) * SM_BUF_H);
        const uint32_t* Bi = (const uint32_t*)(sm + (2 * buf + 1) * SM_BUF_H);
        #pragma unroll
        for (int ks = 0; ks < 2; ks++) {
            int ac = ks * 8 + (lane & 3);
            uint32_t a[4][4], b[8][2];
            #pragma unroll
            for (int mi = 0; mi < 4; mi++) {
                const uint32_t* p0 = Ai + (size_t)(arowL + mi * 16) * PADW + ac;
                a[mi][0] = p0[0];
                a[mi][1] = p0[8 * PADW];
                a[mi][2] = p0[4];
                a[mi][3] = p0[8 * PADW + 4];
            }
            #pragma unroll
            for (int ni = 0; ni < 8; ni++) {
                const uint32_t* p0 = Bi + (size_t)(browL + ni * 8) * PADW + ac;
                b[ni][0] = p0[0];
                b[ni][1] = p0[4];
            }
            #pragma unroll
            for (int mi = 0; mi < 4; mi++)
                #pragma unroll
                for (int ni = 0; ni < 8; ni++)
                    mma_f16(acc[mi][ni], a[mi], b[ni]);
        }
        __syncthreads();
    }

    // -------- epilogue --------
    float psum = 0.f, psq = 0.f;
    #pragma unroll
    for (int mi = 0; mi < 4; mi++) {
        #pragma unroll
        for (int ni = 0; ni < 8; ni++) {
            int r0 = m0 + wm + mi * 16 + (lane >> 2);
            int cc = n0 + wn + ni * 8 + (lane & 3) * 2;
            #pragma unroll
            for (int h = 0; h < 2; h++) {
                int gr = r0 + h * 8;
                float v0 = p.alpha * acc[mi][ni][h * 2 + 0];
                float v1 = p.alpha * acc[mi][ni][h * 2 + 1];
                if (EPI == 1) {
                    v0 += p.bias[cc]; v1 += p.bias[cc + 1];
                    v0 = 0.5f * v0 * (1.f + erff(v0 * 0.70710678118654752f));
                    v1 = 0.5f * v1 * (1.f + erff(v1 * 0.70710678118654752f));
                }
                if (EPI == 2) {
                    if (p.bias) { v0 += p.bias[cc]; v1 += p.bias[cc + 1]; }
                    const float* ap = p.add + (long)z * p.sAdd + (size_t)gr * p.ldAdd + cc;
                    float2 av = *(const float2*)ap;
                    v0 += av.x; v1 += av.y;
                }
                if (EPI == 3) { psum += v0 + v1; psq += v0 * v0 + v1 * v1; }
                if (OUTH) {
                    __half* Cz = (__half*)p.C + (long)z * p.sC;
                    *(__half2*)&Cz[(size_t)gr * p.ldc + cc] = __floats2half2_rn(v0, v1);
                } else {
                    float* Cz = (float*)p.C + (long)z * p.sC;
                    *(float2*)&Cz[(size_t)gr * p.ldc + cc] = make_float2(v0, v1);
                }
            }
        }
    }
    if (EPI == 3) {
        #pragma unroll
        for (int o = 16; o > 0; o >>= 1) {
            psum += __shfl_down_sync(0xffffffffu, psum, o);
            psq  += __shfl_down_sync(0xffffffffu, psq,  o);
        }
        __syncthreads();
        if (lane == 0) { smf[w] = psum; smf[8 + w] = psq; }
        __syncthreads();
        if (t == 0) {
            float s = 0.f, ss = 0.f;
            #pragma unroll
            for (int i = 0; i < 4; i++) { s += smf[i]; ss += smf[8 + i]; }
            int idx = (z * 4 + blockIdx.y) * gridDim.x + blockIdx.x;
            p.part[idx * 2] = s;
            p.part[idx * 2 + 1] = ss;
        }
    }
}

// ---------------- TN GEMM (tf32, fp32 in, half out): Gt ---------------------
#define PADK 132
#define SM_BUF_TN (32*PADK)
#define SM_TOTAL_TN (NSTAGE*2*SM_BUF_TN*4)

__global__ void __launch_bounds__(128, 2) gemm_mma_tn(TCP p)
{
    extern __shared__ float sm[];
    uint32_t sb = smem_u32(sm);

    int t = threadIdx.x, lane = t & 31, w = t >> 5;
    int z = blockIdx.z;
    int m0 = blockIdx.y * BM, n0 = blockIdx.x * 128;
    const float* Ab = (const float*)p.A + (long)z * p.sA + m0;
    const float* Bb = (const float*)p.B + (long)z * p.sB + n0;
    __half* Cz = (__half*)p.C + (long)z * p.sC;

    int nIt = p.K >> 5;
    int kk = 0;

    auto issue = [&](int buf) {
        const float* Ag = Ab + (size_t)kk * p.lda;
        const float* Bg = Bb + (size_t)kk * p.ldb;
        uint32_t da = sb + (2 * buf) * SM_BUF_TN * 4;
        uint32_t db = sb + (2 * buf + 1) * SM_BUF_TN * 4;
        #pragma unroll
        for (int i = 0; i < 8; i++) {
            int task = t + i * 128, kr = task >> 5, q = task & 31;
            CP_ASYNC16(da + (kr * PADK + q * 4) * 4, Ag + (size_t)kr * p.lda + q * 4);
            CP_ASYNC16(db + (kr * PADK + q * 4) * 4, Bg + (size_t)kr * p.ldb + q * 4);
        }
        CP_COMMIT();
        kk += 32;
    };

    issue(0);
    if (nIt > 1) issue(1);

    int wm = (w >> 1) * 64, wn = (w & 1) * 64;
    float acc[4][8][4] = {};
    int arowL = wm + (lane >> 2), browL = wn + (lane >> 2);

    for (int it = 0; it < nIt; it++) {
        int buf = it % NSTAGE;
        if (it + 2 < nIt) issue((it + 2) % NSTAGE);
        else CP_COMMIT();
        CP_WAIT2();
        __syncthreads();

        const uint32_t* Ai = (const uint32_t*)(sm + (2 * buf) * SM_BUF_TN);
        const uint32_t* Bi = (const uint32_t*)(sm + (2 * buf + 1) * SM_BUF_TN);
        #pragma unroll
        for (int ks = 0; ks < 4; ks++) {
            int ac = ks * 8 + (lane & 3);
            uint32_t a[4][4], b[8][2];
            #pragma unroll
            for (int mi = 0; mi < 4; mi++) {
                const uint32_t* p0 = Ai + (size_t)ac * PADK + arowL + mi * 16;
                a[mi][0] = p0[0];
                a[mi][1] = p0[8];
                a[mi][2] = p0[4 * PADK];
                a[mi][3] = p0[4 * PADK + 8];
            }
            #pragma unroll
            for (int ni = 0; ni < 8; ni++) {
                const uint32_t* p0 = Bi + (size_t)ac * PADK + browL + ni * 8;
                b[ni][0] = p0[0];
                b[ni][1] = p0[4 * PADK];
            }
            #pragma unroll
            for (int mi = 0; mi < 4; mi++)
                #pragma unroll
                for (int ni = 0; ni < 8; ni++)
                    mma_tf32(acc[mi][ni], a[mi], b[ni]);
        }
        __syncthreads();
    }

    #pragma unroll
    for (int mi = 0; mi < 4; mi++) {
        #pragma unroll
        for (int ni = 0; ni < 8; ni++) {
            int r0 = m0 + wm + mi * 16 + (lane >> 2);
            int cc = n0 + wn + ni * 8 + (lane & 3) * 2;
            #pragma unroll
            for (int h = 0; h < 2; h++) {
                int gr = r0 + h * 8;
                *(__half2*)&Cz[(size_t)gr * p.ldc + cc] =
                    __floats2half2_rn(acc[mi][ni][h * 2 + 0], acc[mi][ni][h * 2 + 1]);
            }
        }
    }
}

// ---------------- transpose fp32 -> half ----------------
__global__ void __launch_bounds__(256) transpose_h_kernel(
    const float* __restrict__ in, __half* __restrict__ out, int rows, int cols)
{
    __shared__ float tile[32][33];
    long zo = (long)blockIdx.z * rows * cols;
    const float* ip = in + zo;
    __half* op = out + zo;
    int c0 = blockIdx.x * 32, r0 = blockIdx.y * 32;
    int tx = threadIdx.x & 31, ty = threadIdx.x >> 5;
    #pragma unroll
    for (int i = 0; i < 4; i++)
        tile[ty + i * 8][tx] = ip[(size_t)(r0 + ty + i * 8) * cols + c0 + tx];
    __syncthreads();
    #pragma unroll
    for (int i = 0; i < 4; i++)
        op[(size_t)(c0 + ty + i * 8) * rows + r0 + tx] = __float2half(tile[tx][ty + i * 8]);
}

// ---------------- fp32 -> half convert (Wv) ----------------
__global__ void __launch_bounds__(256) f2h_kernel(const float4* __restrict__ in,
                                                  __half2* __restrict__ out, int n4)
{
    int i = blockIdx.x * 256 + threadIdx.x;
    if (i < n4) {
        float4 v = in[i];
        out[2 * i]     = __floats2half2_rn(v.x, v.y);
        out[2 * i + 1] = __floats2half2_rn(v.z, v.w);
    }
}

// ---------------- reductions ----------------
template <int NW>
__device__ __forceinline__ float bRSum(float v, float* sbuf) {
    #pragma unroll
    for (int o = 16; o > 0; o >>= 1) v += __shfl_down_sync(0xffffffffu, v, o);
    int lane = threadIdx.x & 31, w = threadIdx.x >> 5;
    if (lane == 0) sbuf[w] = v;
    __syncthreads();
    float tot = 0.f;
    #pragma unroll
    for (int i = 0; i < NW; i++) tot += sbuf[i];
    __syncthreads();
    return tot;
}
template <int NW>
__device__ __forceinline__ float bRMax(float v, float* sbuf) {
    #pragma unroll
    for (int o = 16; o > 0; o >>= 1) v = fmaxf(v, __shfl_xor_sync(0xffffffffu, v, o));
    int lane = threadIdx.x & 31, w = threadIdx.x >> 5;
    if (lane == 0) sbuf[w] = v;
    __syncthreads();
    float tot = -1e30f;
    #pragma unroll
    for (int i = 0; i < NW; i++) tot = fmaxf(tot, sbuf[i]);
    __syncthreads();
    return tot;
}

// ---------------- LN kernels ----------------
__global__ void __launch_bounds__(256) ln_all_kernel(
    const float* __restrict__ e1, const float* __restrict__ e2, const float* __restrict__ e3,
    const float* __restrict__ g1, const float* __restrict__ b1,
    const float* __restrict__ ga, const float* __restrict__ ba,
    float* __restrict__ X, __half* __restrict__ Xh, float* __restrict__ cx2)
{
    __shared__ float xs[KVD];
    __shared__ float red[8];
    int tok = blockIdx.x, t = threadIdx.x;
    const float* p1 = e1 + (size_t)tok * 256;
    const float* p2 = e2 + (size_t)tok * 512;
    const float* p3 = e3 + (size_t)tok * 1024;
    xs[t] = p1[t];
    xs[256 + t] = p2[t];
    xs[512 + t] = p2[256 + t];
    #pragma unroll
    for (int i = 0; i < 4; i++) xs[768 + t + i * 256] = p3[t + i * 256];
    __syncthreads();
    float s = 0.f, ss = 0.f, s2 = 0.f, ss2 = 0.f;
    for (int i = t; i < KVD; i += 256) { float x = xs[i]; s += x; ss += x * x; }
    for (int i = t; i < 512; i += 256) { float x = xs[256 + i]; s2 += x; ss2 += x * x; }
    s  = bRSum<8>(s,  red);
    ss = bRSum<8>(ss, red);
    s2 = bRSum<8>(s2, red);
    ss2= bRSum<8>(ss2,red);
    float m  = s * (1.f / KVD), r = rsqrtf(ss * (1.f / KVD) - m * m + 1e-6f);
    float m2 = s2 * (1.f / 512.f), r2 = rsqrtf(ss2 * (1.f / 512.f) - m2 * m2 + 1e-6f);
    float* Xo = X + (size_t)tok * KVD;
    __half* Xho = Xh + (size_t)tok * KVD;
    float* co = cx2 + (size_t)tok * 512;
    for (int i = t; i < KVD; i += 256) {
        float v = (xs[i] - m) * r * ga[i] + ba[i];
        Xo[i] = v;
        Xho[i] = __float2half(v);
    }
    for (int i = t; i < 512; i += 256) co[i] = (xs[256 + i] - m2) * r2 * g1[i] + b1[i];
}

__global__ void __launch_bounds__(256) ln512_kernel(
    const float* __restrict__ in, const float* __restrict__ g, const float* __restrict__ b,
    __half* __restrict__ out)
{
    __shared__ float red[8];
    int tok = blockIdx.x, t = threadIdx.x;
    const float* p = in + (size_t)tok * 512;
    float x0 = p[t], x1 = p[t + 256];
    float s = bRSum<8>(x0 + x1, red);
    float ss = bRSum<8>(x0 * x0 + x1 * x1, red);
    float m = s * (1.f / 512.f);
    float r = rsqrtf(ss * (1.f / 512.f) - m * m + 1e-6f);
    __half* o = out + (size_t)tok * 512;
    o[t] = __float2half((x0 - m) * r * g[t] + b[t]);
    o[t + 256] = __float2half((x1 - m) * r * g[t + 256] + b[t + 256]);
}

// ---------------- softmax over KV (half2) ----------------
__global__ void __launch_bounds__(128) softmax_kernel(__half2* __restrict__ S2,
                                                      const float* __restrict__ part)
{
    __shared__ float red[4];
    int row = blockIdx.x, t = threadIdx.x;
    int map = row >> 9;
    float s0 = 0.f, q0 = 0.f;
    const float2* pp = (const float2*)part + map * NTILEMAP;
    #pragma unroll 8
    for (int i = 0; i < NTILEMAP; i++) { float2 v = pp[i]; s0 += v.x; q0 += v.y; }
    float invn = 1.f / (float)MAPELEMS;
    float mean = s0 * invn;
    float r = rsqrtf(q0 * invn - mean * mean + 1e-5f);

    __half2* p = S2 + (size_t)row * (KVD / 2);
    float vx[7], vy[7];
    float mx = -1e30f;
    #pragma unroll
    for (int j = 0; j < 7; j++) {
        float2 f = __half22float2(p[t + j * 128]);
        vx[j] = f.x * r; vy[j] = f.y * r;
        mx = fmaxf(mx, fmaxf(vx[j], vy[j]));
    }
    mx = bRMax<4>(mx, red);
    float s = 0.f;
    #pragma unroll
    for (int j = 0; j < 7; j++) {
        vx[j] = expf(vx[j] - mx); vy[j] = expf(vy[j] - mx);
        s += vx[j] + vy[j];
    }
    s = bRSum<4>(s, red);
    float inv = 1.f / s;
    #pragma unroll
    for (int j = 0; j < 7; j++)
        p[t + j * 128] = __floats2half2_rn(vx[j] * inv, vy[j] * inv);
}

// ---------------- host ----------------
static inline TCP mkP(const void* A, const void* B, void* C,
                      int lda, int ldb, int ldc, int K,
                      long sA, long sB, long sC, int aSel, int bSel,
                      int nseg, long segA, long segB, float alpha,
                      const float* bias, const float* add, int ldAdd, long sAdd,
                      float* part = nullptr)
{
    TCP p; p.A = A; p.B = B; p.C = C; p.lda = lda; p.ldb = ldb; p.ldc = ldc; p.K = K;
    p.sA = sA; p.sB = sB; p.sC = sC; p.aSel = aSel; p.bSel = bSel;
    p.nseg = nseg; p.segA = segA; p.segB = segB; p.alpha = alpha;
    p.bias = bias; p.add = add; p.ldAdd = ldAdd; p.sAdd = sAdd; p.part = part;
    return p;
}

extern "C" void kernel_launch(void* const* d_in, const int* in_sizes, int n_in,
                              void* d_out, int out_size)
{
    const float* emb1   = (const float*)d_in[0];
    const float* emb2   = (const float*)d_in[1];
    const float* emb3   = (const float*)d_in[2];
    const float* Wq     = (const float*)d_in[3];
    const float* Wk     = (const float*)d_in[4];
    const float* Wv     = (const float*)d_in[5];
    const float* Wout   = (const float*)d_in[6];
    const float* ln1_g  = (const float*)d_in[7];
    const float* ln1_b  = (const float*)d_in[8];
    const float* lnall_g= (const float*)d_in[9];
    const float* lnall_b= (const float*)d_in[10];
    const float* lnffn_g= (const float*)d_in[11];
    const float* lnffn_b= (const float*)d_in[12];
    const float* fc1_w  = (const float*)d_in[13];
    const float* fc1_b  = (const float*)d_in[14];
    const float* fc2_w  = (const float*)d_in[15];
    const float* fc2_b  = (const float*)d_in[16];
    float* out = (float*)d_out;

    cudaFuncSetAttribute(gemm_mma<0,1>, cudaFuncAttributeMaxDynamicSharedMemorySize, SM_TOTAL_H);
    cudaFuncSetAttribute(gemm_mma<1,1>, cudaFuncAttributeMaxDynamicSharedMemorySize, SM_TOTAL_H);
    cudaFuncSetAttribute(gemm_mma<2,0>, cudaFuncAttributeMaxDynamicSharedMemorySize, SM_TOTAL_H);
    cudaFuncSetAttribute(gemm_mma<3,1>, cudaFuncAttributeMaxDynamicSharedMemorySize, SM_TOTAL_H);
    cudaFuncSetAttribute(gemm_mma_tn, cudaFuncAttributeMaxDynamicSharedMemorySize, SM_TOTAL_TN);

    float *X, *cx2, *res, *part;
    __half *Xh, *Gt, *T, *S, *Mt, *ctx, *x2, *h1, *WqT, *WkT, *WoutT, *fc1T, *fc2T, *Wvh;
    cudaGetSymbolAddress((void**)&X,    g_X);
    cudaGetSymbolAddress((void**)&Xh,   g_Xh);
    cudaGetSymbolAddress((void**)&cx2,  g_cx2);
    cudaGetSymbolAddress((void**)&Gt,   g_Gt);
    cudaGetSymbolAddress((void**)&T,    g_T);
    cudaGetSymbolAddress((void**)&S,    g_S);
    cudaGetSymbolAddress((void**)&Mt,   g_Mt);
    cudaGetSymbolAddress((void**)&ctx,  g_ctx);
    cudaGetSymbolAddress((void**)&res,  g_res);
    cudaGetSymbolAddress((void**)&x2,   g_x2);
    cudaGetSymbolAddress((void**)&h1,   g_h1);
    cudaGetSymbolAddress((void**)&WqT,  g_WqT);
    cudaGetSymbolAddress((void**)&WkT,  g_WkT);
    cudaGetSymbolAddress((void**)&WoutT,g_WoutT);
    cudaGetSymbolAddress((void**)&fc1T, g_fc1T);
    cudaGetSymbolAddress((void**)&fc2T, g_fc2T);
    cudaGetSymbolAddress((void**)&Wvh,  g_Wvh);
    cudaGetSymbolAddress((void**)&part, g_part);

    const long MAPSZ = (long)CC2 * KVD;
    const float inv_sqrt_kv = 1.f / sqrtf((float)KVD);

    // weight transposes (fp32 -> half) + Wv convert
    transpose_h_kernel<<<dim3(16,16,4), 256>>>(Wq, WqT, 512, 512);
    transpose_h_kernel<<<dim3(56,56,4), 256>>>(Wk, WkT, KVD, KVD);
    transpose_h_kernel<<<dim3(16,16,1), 256>>>(Wout, WoutT, 512, 512);
    transpose_h_kernel<<<dim3(64,16,1), 256>>>(fc1_w, fc1T, 512, 2048);
    transpose_h_kernel<<<dim3(16,64,1), 256>>>(fc2_w, fc2T, 2048, 512);
    f2h_kernel<<<(NH*KVD*KVD/4 + 255)/256, 256>>>((const float4*)Wv, (__half2*)Wvh,
                                                  NH*KVD*KVD/4);

    // 1. LayerNorms
    ln_all_kernel<<<NB*NTOK, 256>>>(emb1, emb2, emb3, ln1_g, ln1_b,
                                    lnall_g, lnall_b, X, Xh, cx2);

    // 2. Gt[b][j][c] : TN tf32, M=KVD, N=512, K=1024, half out
    gemm_mma_tn<<<dim3(4,14,8), 128, SM_TOTAL_TN>>>(
        mkP(X, cx2, Gt, KVD, 512, 512, NTOK,
            (long)NTOK*KVD, (long)NTOK*512, (long)KVD*512, 0, 0,
            1, 0, 0, 1.f, nullptr, nullptr, 0, 0));

    // 3. T[z][d][j] : M=512, N=KVD, K=512 (fp16)
    gemm_mma<0,1><<<dim3(14,4,32), 128, SM_TOTAL_H>>>(
        mkP(WqT, Gt, T, 512, 512, KVD, 512,
            (long)512*512, (long)KVD*512, MAPSZ, 1, 2,
            1, 0, 0, 1.f, nullptr, nullptr, 0, 0));

    // 4. S[z][d][k'] : M=512, N=KVD, K=KVD (fp16) + fused IN partial stats
    gemm_mma<3,1><<<dim3(14,4,32), 128, SM_TOTAL_H>>>(
        mkP(T, WkT, S, KVD, KVD, KVD, KVD,
            MAPSZ, (long)KVD*KVD, MAPSZ, 0, 1,
            1, 0, 0, inv_sqrt_kv, nullptr, nullptr, 0, 0, part));

    // 5. probs = softmax(rstd * S), half2 in place
    softmax_kernel<<<NMAPS*512, 128>>>((__half2*)S, part);

    // 6. Mt[b][c][j] : M=512, N=KVD, 4 segs over h (fp16)
    gemm_mma<0,1><<<dim3(14,4,8), 128, SM_TOTAL_H>>>(
        mkP(S, Wvh, Mt, KVD, KVD, KVD, KVD,
            4*MAPSZ, 0, (long)512*KVD, 0, 0,
            4, MAPSZ, (long)KVD*KVD, 0.25f, nullptr, nullptr, 0, 0));

    // 7. ctx[b][t][c] : M=1024, N=512, K=KVD (fp16)
    gemm_mma<0,1><<<dim3(4,8,8), 128, SM_TOTAL_H>>>(
        mkP(Xh, Mt, ctx, KVD, KVD, 512, KVD,
            (long)NTOK*KVD, (long)512*KVD, (long)NTOK*512, 0, 0,
            1, 0, 0, 1.f, nullptr, nullptr, 0, 0));

    // 8. res = ctx @ Wout + emb2 : M=8192, N=512, K=512 (fp16 in, fp32 out)
    gemm_mma<2,0><<<dim3(4,64,1), 128, SM_TOTAL_H>>>(
        mkP(ctx, WoutT, res, 512, 512, 512, 512,
            0, 0, 0, 0, 0, 1, 0, 0, 1.f, nullptr, emb2, 512, 0));

    // 9. x2 = LN(res), half out
    ln512_kernel<<<NB*NTOK, 256>>>(res, lnffn_g, lnffn_b, x2);

    // 10. h1 = gelu(x2 @ fc1 + b1) : M=8192, N=2048, K=512 (fp16)
    gemm_mma<1,1><<<dim3(16,64,1), 128, SM_TOTAL_H>>>(
        mkP(x2, fc1T, h1, 512, 512, 2048, 512,
            0, 0, 0, 0, 0, 1, 0, 0, 1.f, fc1_b, nullptr, 0, 0));

    // 11. out = h1 @ fc2 + b2 + res : M=8192, N=512, K=2048 (fp16 in, fp32 out)
    gemm_mma<2,0><<<dim3(4,64,1), 128, SM_TOTAL_H>>>(
        mkP(h1, fc2T, out, 2048, 2048, 512, 2048,
            0, 0, 0, 0, 0, 1, 0, 0, 1.f, fc2_b, res, 512, 0));
}

// round 14
// speedup vs baseline: 1.8186x; 1.1346x over previous
#include <cuda_runtime.h>
#include <cuda_fp16.h>
#include <math.h>
#include <stdint.h>

#define NB 8
#define NTOK 1024
#define CC2 512
#define KVD 1792
#define NH 4
#define NMAPS (NB*NH)          // 32
#define MAPELEMS (CC2*KVD)     // 917504
#define NTILEMAP 56            // 14 x 4 stat tiles per map
#define NPART (NMAPS*NTILEMAP)

// ---------------- scratch ----------------
__device__ __align__(128) float  g_X   [NB*NTOK*KVD];     // fp32 (TN Gt)
__device__ __align__(128) __half g_Xh  [NB*NTOK*KVD];     // half (ctx GEMM)
__device__ __align__(128) float  g_cx2 [NB*NTOK*CC2];     // fp32 (TN Gt)
__device__ __align__(128) __half g_Gt  [NB*KVD*CC2];
__device__ __align__(128) __half g_T   [NMAPS*CC2*KVD];
__device__ __align__(128) __half g_S   [NMAPS*CC2*KVD];
__device__ __align__(128) __half g_Mt  [NB*CC2*KVD];
__device__ __align__(128) __half g_ctx [NB*NTOK*CC2];
__device__ __align__(128) float  g_res [NB*NTOK*CC2];
__device__ __align__(128) __half g_x2  [NB*NTOK*CC2];
__device__ __align__(128) __half g_h1  [NB*NTOK*CC2*4];
__device__ __align__(128) __half g_WqT [NH*CC2*CC2];
__device__ __align__(128) __half g_WkT [NH*KVD*KVD];
__device__ __align__(128) __half g_WoutT[CC2*CC2];
__device__ __align__(128) __half g_fc1T[CC2*4*CC2];
__device__ __align__(128) __half g_fc2T[CC2*CC2*4];
__device__ __align__(128) __half g_Wvh [NH*KVD*KVD];
__device__ __align__(128) float  g_part[NPART*2];

// ---------------- helpers ----------------
__device__ __forceinline__ uint32_t smem_u32(const void* p) {
    uint32_t a;
    asm("{ .reg .u64 t; cvta.to.shared.u64 t, %1; cvt.u32.u64 %0, t; }" : "=r"(a) : "l"(p));
    return a;
}
#define CP_ASYNC16(sa, ga) \
    asm volatile("cp.async.cg.shared.global [%0], [%1], 16;" :: "r"(sa), "l"(ga) : "memory")
#define CP_COMMIT() asm volatile("cp.async.commit_group;" ::: "memory")
#define CP_WAIT2()  asm volatile("cp.async.wait_group 2;" ::: "memory")
#define CP_WAIT3()  asm volatile("cp.async.wait_group 3;" ::: "memory")

#define LDSM_X4(r0, r1, r2, r3, addr) \
    asm volatile("ldmatrix.sync.aligned.m8n8.x4.shared.b16 {%0,%1,%2,%3}, [%4];" \
        : "=r"(r0), "=r"(r1), "=r"(r2), "=r"(r3) : "r"(addr))

__device__ __forceinline__ void mma_f16(float* c, const uint32_t* a, const uint32_t* b) {
    asm volatile(
        "mma.sync.aligned.m16n8k16.row.col.f32.f16.f16.f32 "
        "{%0,%1,%2,%3}, {%4,%5,%6,%7}, {%8,%9}, {%0,%1,%2,%3};"
        : "+f"(c[0]), "+f"(c[1]), "+f"(c[2]), "+f"(c[3])
        : "r"(a[0]), "r"(a[1]), "r"(a[2]), "r"(a[3]), "r"(b[0]), "r"(b[1]));
}
__device__ __forceinline__ void mma_tf32(float* c, const uint32_t* a, const uint32_t* b) {
    asm volatile(
        "mma.sync.aligned.m16n8k8.row.col.f32.tf32.tf32.f32 "
        "{%0,%1,%2,%3}, {%4,%5,%6,%7}, {%8,%9}, {%0,%1,%2,%3};"
        : "+f"(c[0]), "+f"(c[1]), "+f"(c[2]), "+f"(c[3])
        : "r"(a[0]), "r"(a[1]), "r"(a[2]), "r"(a[3]), "r"(b[0]), "r"(b[1]));
}

// ---------------- fp16 tensor-core GEMM: D = alpha*sum_seg A[M,K]@B[N,K]^T --
// CTA 128x128, 4 warps 2x2, warp tile 64x64. K-chunk 32 halves (2 k16 steps).
// Fragments via ldmatrix.x4; 4-stage cp.async pipeline.
#define BM 128
#define PADH 40                       // halves per smem row
#define SM_BUF_H (128*PADH)           // halves per operand buffer (5120)
#define NSTAGE 4
#define SM_TOTAL_H (NSTAGE*2*SM_BUF_H*2)   // 81920 bytes

struct TCP {
    const void *A, *B; void *C;
    int lda, ldb, ldc, K;
    long sA, sB, sC;
    int aSel, bSel, nseg;
    long segA, segB;
    float alpha;
    const float* bias;
    const float* add; int ldAdd; long sAdd;
    float* part;
};

// EPI: 0 plain; 1 bias+gelu; 2 (+bias)+add; 3 plain + IN partial stats
// OUTH: 1 = half2 store, 0 = float2 store
template <int EPI, int OUTH>
__global__ void __launch_bounds__(128, 2) gemm_mma(TCP p)
{
    extern __shared__ float smf[];
    __half* sm = (__half*)smf;
    uint32_t sb = smem_u32(sm);

    int t = threadIdx.x, lane = t & 31, w = t >> 5;
    int z = blockIdx.z;
    int m0 = blockIdx.y * BM, n0 = blockIdx.x * 128;
    int az = p.aSel == 0 ? z : (p.aSel == 1 ? (z & 3) : (z >> 2));
    int bz = p.bSel == 0 ? z : (p.bSel == 1 ? (z & 3) : (z >> 2));
    const __half* Ab = (const __half*)p.A + (long)az * p.sA + (size_t)m0 * p.lda;
    const __half* Bb = (const __half*)p.B + (long)bz * p.sB + (size_t)n0 * p.ldb;

    int kIters = p.K >> 5;
    int nIt = kIters * p.nseg;
    int seg = 0, kk = 0;

    auto issue = [&](int buf) {
        const __half* Ag = Ab + (long)seg * p.segA + kk;
        const __half* Bg = Bb + (long)seg * p.segB + kk;
        uint32_t da = sb + (2 * buf) * SM_BUF_H * 2;
        uint32_t db = sb + (2 * buf + 1) * SM_BUF_H * 2;
        #pragma unroll
        for (int i = 0; i < 4; i++) {
            int task = t + i * 128, row = task >> 2, q = task & 3;
            CP_ASYNC16(da + row * (PADH * 2) + q * 16, Ag + (size_t)row * p.lda + q * 8);
            CP_ASYNC16(db + row * (PADH * 2) + q * 16, Bg + (size_t)row * p.ldb + q * 8);
        }
        CP_COMMIT();
        kk += 32; if (kk == p.K) { kk = 0; seg++; }
    };

    issue(0);
    if (nIt > 1) issue(1);
    if (nIt > 2) issue(2);

    int wm = (w >> 1) * 64, wn = (w & 1) * 64;
    float acc[4][8][4] = {};

    // ldmatrix lane addressing (byte offsets within an operand buffer)
    int rA  = (lane & 7) + ((lane >> 3) & 1) * 8;     // row within 16-row tile
    int kcA = (lane >> 4) * 8;                        // k-halves offset (0 or 8)
    int rB  = (lane & 7) + ((lane >> 4) & 1) * 8;
    int kcB = ((lane >> 3) & 1) * 8;
    uint32_t aoff[4], boff[4];
    #pragma unroll
    for (int mi = 0; mi < 4; mi++)
        aoff[mi] = ((wm + mi * 16 + rA) * PADH + kcA) * 2;
    #pragma unroll
    for (int np = 0; np < 4; np++)
        boff[np] = ((wn + np * 16 + rB) * PADH + kcB) * 2;

    for (int it = 0; it < nIt; it++) {
        int buf = it % NSTAGE;
        if (it + 3 < nIt) issue((it + 3) % NSTAGE);
        else CP_COMMIT();
        CP_WAIT3();
        __syncthreads();

        uint32_t da = sb + (2 * buf) * SM_BUF_H * 2;
        uint32_t db = sb + (2 * buf + 1) * SM_BUF_H * 2;
        #pragma unroll
        for (int ks = 0; ks < 2; ks++) {
            uint32_t a[4][4], b[8][2];
            #pragma unroll
            for (int mi = 0; mi < 4; mi++)
                LDSM_X4(a[mi][0], a[mi][1], a[mi][2], a[mi][3], da + aoff[mi] + ks * 32);
            #pragma unroll
            for (int np = 0; np < 4; np++)
                LDSM_X4(b[2*np][0], b[2*np][1], b[2*np+1][0], b[2*np+1][1],
                        db + boff[np] + ks * 32);
            #pragma unroll
            for (int mi = 0; mi < 4; mi++)
                #pragma unroll
                for (int ni = 0; ni < 8; ni++)
                    mma_f16(acc[mi][ni], a[mi], b[ni]);
        }
        __syncthreads();
    }

    // -------- epilogue --------
    float psum = 0.f, psq = 0.f;
    #pragma unroll
    for (int mi = 0; mi < 4; mi++) {
        #pragma unroll
        for (int ni = 0; ni < 8; ni++) {
            int r0 = m0 + wm + mi * 16 + (lane >> 2);
            int cc = n0 + wn + ni * 8 + (lane & 3) * 2;
            #pragma unroll
            for (int h = 0; h < 2; h++) {
                int gr = r0 + h * 8;
                float v0 = p.alpha * acc[mi][ni][h * 2 + 0];
                float v1 = p.alpha * acc[mi][ni][h * 2 + 1];
                if (EPI == 1) {
                    v0 += p.bias[cc]; v1 += p.bias[cc + 1];
                    v0 = 0.5f * v0 * (1.f + erff(v0 * 0.70710678118654752f));
                    v1 = 0.5f * v1 * (1.f + erff(v1 * 0.70710678118654752f));
                }
                if (EPI == 2) {
                    if (p.bias) { v0 += p.bias[cc]; v1 += p.bias[cc + 1]; }
                    const float* ap = p.add + (long)z * p.sAdd + (size_t)gr * p.ldAdd + cc;
                    float2 av = *(const float2*)ap;
                    v0 += av.x; v1 += av.y;
                }
                if (EPI == 3) { psum += v0 + v1; psq += v0 * v0 + v1 * v1; }
                if (OUTH) {
                    __half* Cz = (__half*)p.C + (long)z * p.sC;
                    *(__half2*)&Cz[(size_t)gr * p.ldc + cc] = __floats2half2_rn(v0, v1);
                } else {
                    float* Cz = (float*)p.C + (long)z * p.sC;
                    *(float2*)&Cz[(size_t)gr * p.ldc + cc] = make_float2(v0, v1);
                }
            }
        }
    }
    if (EPI == 3) {
        #pragma unroll
        for (int o = 16; o > 0; o >>= 1) {
            psum += __shfl_down_sync(0xffffffffu, psum, o);
            psq  += __shfl_down_sync(0xffffffffu, psq,  o);
        }
        __syncthreads();
        if (lane == 0) { smf[w] = psum; smf[8 + w] = psq; }
        __syncthreads();
        if (t == 0) {
            float s = 0.f, ss = 0.f;
            #pragma unroll
            for (int i = 0; i < 4; i++) { s += smf[i]; ss += smf[8 + i]; }
            int idx = (z * 4 + blockIdx.y) * gridDim.x + blockIdx.x;
            p.part[idx * 2] = s;
            p.part[idx * 2 + 1] = ss;
        }
    }
}

// ---------------- TN GEMM (tf32, fp32 in, half out): Gt ---------------------
#define PADK 132
#define NSTAGE_TN 3
#define SM_BUF_TN (32*PADK)
#define SM_TOTAL_TN (NSTAGE_TN*2*SM_BUF_TN*4)

__global__ void __launch_bounds__(128, 2) gemm_mma_tn(TCP p)
{
    extern __shared__ float sm[];
    uint32_t sb = smem_u32(sm);

    int t = threadIdx.x, lane = t & 31, w = t >> 5;
    int z = blockIdx.z;
    int m0 = blockIdx.y * BM, n0 = blockIdx.x * 128;
    const float* Ab = (const float*)p.A + (long)z * p.sA + m0;
    const float* Bb = (const float*)p.B + (long)z * p.sB + n0;
    __half* Cz = (__half*)p.C + (long)z * p.sC;

    int nIt = p.K >> 5;
    int kk = 0;

    auto issue = [&](int buf) {
        const float* Ag = Ab + (size_t)kk * p.lda;
        const float* Bg = Bb + (size_t)kk * p.ldb;
        uint32_t da = sb + (2 * buf) * SM_BUF_TN * 4;
        uint32_t db = sb + (2 * buf + 1) * SM_BUF_TN * 4;
        #pragma unroll
        for (int i = 0; i < 8; i++) {
            int task = t + i * 128, kr = task >> 5, q = task & 31;
            CP_ASYNC16(da + (kr * PADK + q * 4) * 4, Ag + (size_t)kr * p.lda + q * 4);
            CP_ASYNC16(db + (kr * PADK + q * 4) * 4, Bg + (size_t)kr * p.ldb + q * 4);
        }
        CP_COMMIT();
        kk += 32;
    };

    issue(0);
    if (nIt > 1) issue(1);

    int wm = (w >> 1) * 64, wn = (w & 1) * 64;
    float acc[4][8][4] = {};
    int arowL = wm + (lane >> 2), browL = wn + (lane >> 2);

    for (int it = 0; it < nIt; it++) {
        int buf = it % NSTAGE_TN;
        if (it + 2 < nIt) issue((it + 2) % NSTAGE_TN);
        else CP_COMMIT();
        CP_WAIT2();
        __syncthreads();

        const uint32_t* Ai = (const uint32_t*)(sm + (2 * buf) * SM_BUF_TN);
        const uint32_t* Bi = (const uint32_t*)(sm + (2 * buf + 1) * SM_BUF_TN);
        #pragma unroll
        for (int ks = 0; ks < 4; ks++) {
            int ac = ks * 8 + (lane & 3);
            uint32_t a[4][4], b[8][2];
            #pragma unroll
            for (int mi = 0; mi < 4; mi++) {
                const uint32_t* p0 = Ai + (size_t)ac * PADK + arowL + mi * 16;
                a[mi][0] = p0[0];
                a[mi][1] = p0[8];
                a[mi][2] = p0[4 * PADK];
                a[mi][3] = p0[4 * PADK + 8];
            }
            #pragma unroll
            for (int ni = 0; ni < 8; ni++) {
                const uint32_t* p0 = Bi + (size_t)ac * PADK + browL + ni * 8;
                b[ni][0] = p0[0];
                b[ni][1] = p0[4 * PADK];
            }
            #pragma unroll
            for (int mi = 0; mi < 4; mi++)
                #pragma unroll
                for (int ni = 0; ni < 8; ni++)
                    mma_tf32(acc[mi][ni], a[mi], b[ni]);
        }
        __syncthreads();
    }

    #pragma unroll
    for (int mi = 0; mi < 4; mi++) {
        #pragma unroll
        for (int ni = 0; ni < 8; ni++) {
            int r0 = m0 + wm + mi * 16 + (lane >> 2);
            int cc = n0 + wn + ni * 8 + (lane & 3) * 2;
            #pragma unroll
            for (int h = 0; h < 2; h++) {
                int gr = r0 + h * 8;
                *(__half2*)&Cz[(size_t)gr * p.ldc + cc] =
                    __floats2half2_rn(acc[mi][ni][h * 2 + 0], acc[mi][ni][h * 2 + 1]);
            }
        }
    }
}

// ---------------- transpose fp32 -> half ----------------
__global__ void __launch_bounds__(256) transpose_h_kernel(
    const float* __restrict__ in, __half* __restrict__ out, int rows, int cols)
{
    __shared__ float tile[32][33];
    long zo = (long)blockIdx.z * rows * cols;
    const float* ip = in + zo;
    __half* op = out + zo;
    int c0 = blockIdx.x * 32, r0 = blockIdx.y * 32;
    int tx = threadIdx.x & 31, ty = threadIdx.x >> 5;
    #pragma unroll
    for (int i = 0; i < 4; i++)
        tile[ty + i * 8][tx] = ip[(size_t)(r0 + ty + i * 8) * cols + c0 + tx];
    __syncthreads();
    #pragma unroll
    for (int i = 0; i < 4; i++)
        op[(size_t)(c0 + ty + i * 8) * rows + r0 + tx] = __float2half(tile[tx][ty + i * 8]);
}

// ---------------- fp32 -> half convert (Wv) ----------------
__global__ void __launch_bounds__(256) f2h_kernel(const float4* __restrict__ in,
                                                  __half2* __restrict__ out, int n4)
{
    int i = blockIdx.x * 256 + threadIdx.x;
    if (i < n4) {
        float4 v = in[i];
        out[2 * i]     = __floats2half2_rn(v.x, v.y);
        out[2 * i + 1] = __floats2half2_rn(v.z, v.w);
    }
}

// ---------------- reductions ----------------
template <int NW>
__device__ __forceinline__ float bRSum(float v, float* sbuf) {
    #pragma unroll
    for (int o = 16; o > 0; o >>= 1) v += __shfl_down_sync(0xffffffffu, v, o);
    int lane = threadIdx.x & 31, w = threadIdx.x >> 5;
    if (lane == 0) sbuf[w] = v;
    __syncthreads();
    float tot = 0.f;
    #pragma unroll
    for (int i = 0; i < NW; i++) tot += sbuf[i];
    __syncthreads();
    return tot;
}
template <int NW>
__device__ __forceinline__ float bRMax(float v, float* sbuf) {
    #pragma unroll
    for (int o = 16; o > 0; o >>= 1) v = fmaxf(v, __shfl_xor_sync(0xffffffffu, v, o));
    int lane = threadIdx.x & 31, w = threadIdx.x >> 5;
    if (lane == 0) sbuf[w] = v;
    __syncthreads();
    float tot = -1e30f;
    #pragma unroll
    for (int i = 0; i < NW; i++) tot = fmaxf(tot, sbuf[i]);
    __syncthreads();
    return tot;
}

// ---------------- LN kernels ----------------
__global__ void __launch_bounds__(256) ln_all_kernel(
    const float* __restrict__ e1, const float* __restrict__ e2, const float* __restrict__ e3,
    const float* __restrict__ g1, const float* __restrict__ b1,
    const float* __restrict__ ga, const float* __restrict__ ba,
    float* __restrict__ X, __half* __restrict__ Xh, float* __restrict__ cx2)
{
    __shared__ float xs[KVD];
    __shared__ float red[8];
    int tok = blockIdx.x, t = threadIdx.x;
    const float* p1 = e1 + (size_t)tok * 256;
    const float* p2 = e2 + (size_t)tok * 512;
    const float* p3 = e3 + (size_t)tok * 1024;
    xs[t] = p1[t];
    xs[256 + t] = p2[t];
    xs[512 + t] = p2[256 + t];
    #pragma unroll
    for (int i = 0; i < 4; i++) xs[768 + t + i * 256] = p3[t + i * 256];
    __syncthreads();
    float s = 0.f, ss = 0.f, s2 = 0.f, ss2 = 0.f;
    for (int i = t; i < KVD; i += 256) { float x = xs[i]; s += x; ss += x * x; }
    for (int i = t; i < 512; i += 256) { float x = xs[256 + i]; s2 += x; ss2 += x * x; }
    s  = bRSum<8>(s,  red);
    ss = bRSum<8>(ss, red);
    s2 = bRSum<8>(s2, red);
    ss2= bRSum<8>(ss2,red);
    float m  = s * (1.f / KVD), r = rsqrtf(ss * (1.f / KVD) - m * m + 1e-6f);
    float m2 = s2 * (1.f / 512.f), r2 = rsqrtf(ss2 * (1.f / 512.f) - m2 * m2 + 1e-6f);
    float* Xo = X + (size_t)tok * KVD;
    __half* Xho = Xh + (size_t)tok * KVD;
    float* co = cx2 + (size_t)tok * 512;
    for (int i = t; i < KVD; i += 256) {
        float v = (xs[i] - m) * r * ga[i] + ba[i];
        Xo[i] = v;
        Xho[i] = __float2half(v);
    }
    for (int i = t; i < 512; i += 256) co[i] = (xs[256 + i] - m2) * r2 * g1[i] + b1[i];
}

__global__ void __launch_bounds__(256) ln512_kernel(
    const float* __restrict__ in, const float* __restrict__ g, const float* __restrict__ b,
    __half* __restrict__ out)
{
    __shared__ float red[8];
    int tok = blockIdx.x, t = threadIdx.x;
    const float* p = in + (size_t)tok * 512;
    float x0 = p[t], x1 = p[t + 256];
    float s = bRSum<8>(x0 + x1, red);
    float ss = bRSum<8>(x0 * x0 + x1 * x1, red);
    float m = s * (1.f / 512.f);
    float r = rsqrtf(ss * (1.f / 512.f) - m * m + 1e-6f);
    __half* o = out + (size_t)tok * 512;
    o[t] = __float2half((x0 - m) * r * g[t] + b[t]);
    o[t + 256] = __float2half((x1 - m) * r * g[t + 256] + b[t + 256]);
}

// ---------------- softmax over KV (half2) ----------------
__global__ void __launch_bounds__(128) softmax_kernel(__half2* __restrict__ S2,
                                                      const float* __restrict__ part)
{
    __shared__ float red[4];
    int row = blockIdx.x, t = threadIdx.x;
    int map = row >> 9;
    float s0 = 0.f, q0 = 0.f;
    const float2* pp = (const float2*)part + map * NTILEMAP;
    #pragma unroll 8
    for (int i = 0; i < NTILEMAP; i++) { float2 v = pp[i]; s0 += v.x; q0 += v.y; }
    float invn = 1.f / (float)MAPELEMS;
    float mean = s0 * invn;
    float r = rsqrtf(q0 * invn - mean * mean + 1e-5f);

    __half2* p = S2 + (size_t)row * (KVD / 2);
    float vx[7], vy[7];
    float mx = -1e30f;
    #pragma unroll
    for (int j = 0; j < 7; j++) {
        float2 f = __half22float2(p[t + j * 128]);
        vx[j] = f.x * r; vy[j] = f.y * r;
        mx = fmaxf(mx, fmaxf(vx[j], vy[j]));
    }
    mx = bRMax<4>(mx, red);
    float s = 0.f;
    #pragma unroll
    for (int j = 0; j < 7; j++) {
        vx[j] = expf(vx[j] - mx); vy[j] = expf(vy[j] - mx);
        s += vx[j] + vy[j];
    }
    s = bRSum<4>(s, red);
    float inv = 1.f / s;
    #pragma unroll
    for (int j = 0; j < 7; j++)
        p[t + j * 128] = __floats2half2_rn(vx[j] * inv, vy[j] * inv);
}

// ---------------- host ----------------
static inline TCP mkP(const void* A, const void* B, void* C,
                      int lda, int ldb, int ldc, int K,
                      long sA, long sB, long sC, int aSel, int bSel,
                      int nseg, long segA, long segB, float alpha,
                      const float* bias, const float* add, int ldAdd, long sAdd,
                      float* part = nullptr)
{
    TCP p; p.A = A; p.B = B; p.C = C; p.lda = lda; p.ldb = ldb; p.ldc = ldc; p.K = K;
    p.sA = sA; p.sB = sB; p.sC = sC; p.aSel = aSel; p.bSel = bSel;
    p.nseg = nseg; p.segA = segA; p.segB = segB; p.alpha = alpha;
    p.bias = bias; p.add = add; p.ldAdd = ldAdd; p.sAdd = sAdd; p.part = part;
    return p;
}

extern "C" void kernel_launch(void* const* d_in, const int* in_sizes, int n_in,
                              void* d_out, int out_size)
{
    const float* emb1   = (const float*)d_in[0];
    const float* emb2   = (const float*)d_in[1];
    const float* emb3   = (const float*)d_in[2];
    const float* Wq     = (const float*)d_in[3];
    const float* Wk     = (const float*)d_in[4];
    const float* Wv     = (const float*)d_in[5];
    const float* Wout   = (const float*)d_in[6];
    const float* ln1_g  = (const float*)d_in[7];
    const float* ln1_b  = (const float*)d_in[8];
    const float* lnall_g= (const float*)d_in[9];
    const float* lnall_b= (const float*)d_in[10];
    const float* lnffn_g= (const float*)d_in[11];
    const float* lnffn_b= (const float*)d_in[12];
    const float* fc1_w  = (const float*)d_in[13];
    const float* fc1_b  = (const float*)d_in[14];
    const float* fc2_w  = (const float*)d_in[15];
    const float* fc2_b  = (const float*)d_in[16];
    float* out = (float*)d_out;

    cudaFuncSetAttribute(gemm_mma<0,1>, cudaFuncAttributeMaxDynamicSharedMemorySize, SM_TOTAL_H);
    cudaFuncSetAttribute(gemm_mma<1,1>, cudaFuncAttributeMaxDynamicSharedMemorySize, SM_TOTAL_H);
    cudaFuncSetAttribute(gemm_mma<2,0>, cudaFuncAttributeMaxDynamicSharedMemorySize, SM_TOTAL_H);
    cudaFuncSetAttribute(gemm_mma<3,1>, cudaFuncAttributeMaxDynamicSharedMemorySize, SM_TOTAL_H);
    cudaFuncSetAttribute(gemm_mma_tn, cudaFuncAttributeMaxDynamicSharedMemorySize, SM_TOTAL_TN);

    float *X, *cx2, *res, *part;
    __half *Xh, *Gt, *T, *S, *Mt, *ctx, *x2, *h1, *WqT, *WkT, *WoutT, *fc1T, *fc2T, *Wvh;
    cudaGetSymbolAddress((void**)&X,    g_X);
    cudaGetSymbolAddress((void**)&Xh,   g_Xh);
    cudaGetSymbolAddress((void**)&cx2,  g_cx2);
    cudaGetSymbolAddress((void**)&Gt,   g_Gt);
    cudaGetSymbolAddress((void**)&T,    g_T);
    cudaGetSymbolAddress((void**)&S,    g_S);
    cudaGetSymbolAddress((void**)&Mt,   g_Mt);
    cudaGetSymbolAddress((void**)&ctx,  g_ctx);
    cudaGetSymbolAddress((void**)&res,  g_res);
    cudaGetSymbolAddress((void**)&x2,   g_x2);
    cudaGetSymbolAddress((void**)&h1,   g_h1);
    cudaGetSymbolAddress((void**)&WqT,  g_WqT);
    cudaGetSymbolAddress((void**)&WkT,  g_WkT);
    cudaGetSymbolAddress((void**)&WoutT,g_WoutT);
    cudaGetSymbolAddress((void**)&fc1T, g_fc1T);
    cudaGetSymbolAddress((void**)&fc2T, g_fc2T);
    cudaGetSymbolAddress((void**)&Wvh,  g_Wvh);
    cudaGetSymbolAddress((void**)&part, g_part);

    const long MAPSZ = (long)CC2 * KVD;
    const float inv_sqrt_kv = 1.f / sqrtf((float)KVD);

    // weight transposes (fp32 -> half) + Wv convert
    transpose_h_kernel<<<dim3(16,16,4), 256>>>(Wq, WqT, 512, 512);
    transpose_h_kernel<<<dim3(56,56,4), 256>>>(Wk, WkT, KVD, KVD);
    transpose_h_kernel<<<dim3(16,16,1), 256>>>(Wout, WoutT, 512, 512);
    transpose_h_kernel<<<dim3(64,16,1), 256>>>(fc1_w, fc1T, 512, 2048);
    transpose_h_kernel<<<dim3(16,64,1), 256>>>(fc2_w, fc2T, 2048, 512);
    f2h_kernel<<<(NH*KVD*KVD/4 + 255)/256, 256>>>((const float4*)Wv, (__half2*)Wvh,
                                                  NH*KVD*KVD/4);

    // 1. LayerNorms
    ln_all_kernel<<<NB*NTOK, 256>>>(emb1, emb2, emb3, ln1_g, ln1_b,
                                    lnall_g, lnall_b, X, Xh, cx2);

    // 2. Gt[b][j][c] : TN tf32, M=KVD, N=512, K=1024, half out
    gemm_mma_tn<<<dim3(4,14,8), 128, SM_TOTAL_TN>>>(
        mkP(X, cx2, Gt, KVD, 512, 512, NTOK,
            (long)NTOK*KVD, (long)NTOK*512, (long)KVD*512, 0, 0,
            1, 0, 0, 1.f, nullptr, nullptr, 0, 0));

    // 3. T[z][d][j] : M=512, N=KVD, K=512 (fp16)
    gemm_mma<0,1><<<dim3(14,4,32), 128, SM_TOTAL_H>>>(
        mkP(WqT, Gt, T, 512, 512, KVD, 512,
            (long)512*512, (long)KVD*512, MAPSZ, 1, 2,
            1, 0, 0, 1.f, nullptr, nullptr, 0, 0));

    // 4. S[z][d][k'] : M=512, N=KVD, K=KVD (fp16) + fused IN partial stats
    gemm_mma<3,1><<<dim3(14,4,32), 128, SM_TOTAL_H>>>(
        mkP(T, WkT, S, KVD, KVD, KVD, KVD,
            MAPSZ, (long)KVD*KVD, MAPSZ, 0, 1,
            1, 0, 0, inv_sqrt_kv, nullptr, nullptr, 0, 0, part));

    // 5. probs = softmax(rstd * S), half2 in place
    softmax_kernel<<<NMAPS*512, 128>>>((__half2*)S, part);

    // 6. Mt[b][c][j] : M=512, N=KVD, 4 segs over h (fp16)
    gemm_mma<0,1><<<dim3(14,4,8), 128, SM_TOTAL_H>>>(
        mkP(S, Wvh, Mt, KVD, KVD, KVD, KVD,
            4*MAPSZ, 0, (long)512*KVD, 0, 0,
            4, MAPSZ, (long)KVD*KVD, 0.25f, nullptr, nullptr, 0, 0));

    // 7. ctx[b][t][c] : M=1024, N=512, K=KVD (fp16)
    gemm_mma<0,1><<<dim3(4,8,8), 128, SM_TOTAL_H>>>(
        mkP(Xh, Mt, ctx, KVD, KVD, 512, KVD,
            (long)NTOK*KVD, (long)512*KVD, (long)NTOK*512, 0, 0,
            1, 0, 0, 1.f, nullptr, nullptr, 0, 0));

    // 8. res = ctx @ Wout + emb2 : M=8192, N=512, K=512 (fp16 in, fp32 out)
    gemm_mma<2,0><<<dim3(4,64,1), 128, SM_TOTAL_H>>>(
        mkP(ctx, WoutT, res, 512, 512, 512, 512,
            0, 0, 0, 0, 0, 1, 0, 0, 1.f, nullptr, emb2, 512, 0));

    // 9. x2 = LN(res), half out
    ln512_kernel<<<NB*NTOK, 256>>>(res, lnffn_g, lnffn_b, x2);

    // 10. h1 = gelu(x2 @ fc1 + b1) : M=8192, N=2048, K=512 (fp16)
    gemm_mma<1,1><<<dim3(16,64,1), 128, SM_TOTAL_H>>>(
        mkP(x2, fc1T, h1, 512, 512, 2048, 512,
            0, 0, 0, 0, 0, 1, 0, 0, 1.f, fc1_b, nullptr, 0, 0));

    // 11. out = h1 @ fc2 + b2 + res : M=8192, N=512, K=2048 (fp16 in, fp32 out)
    gemm_mma<2,0><<<dim3(4,64,1), 128, SM_TOTAL_H>>>(
        mkP(h1, fc2T, out, 2048, 2048, 512, 2048,
            0, 0, 0, 0, 0, 1, 0, 0, 1.f, fc2_b, res, 512, 0));
}

// round 16
// speedup vs baseline: 1.9303x; 1.0614x over previous
#include <cuda_runtime.h>
#include <cuda_fp16.h>
#include <math.h>
#include <stdint.h>

#define NB 8
#define NTOK 1024
#define CC2 512
#define KVD 1792
#define NH 4
#define NMAPS (NB*NH)          // 32
#define MAPELEMS (CC2*KVD)     // 917504
#define NTILEMAP 56            // 14 x 4 stat tiles per map
#define NPART (NMAPS*NTILEMAP)

// ---------------- scratch ----------------
__device__ __align__(128) __half g_Xh  [NB*NTOK*KVD];
__device__ __align__(128) __half g_c2h [NB*NTOK*CC2];
__device__ __align__(128) __half g_Gt  [NB*KVD*CC2];
__device__ __align__(128) __half g_T   [NMAPS*CC2*KVD];
__device__ __align__(128) __half g_S   [NMAPS*CC2*KVD];
__device__ __align__(128) __half g_Mt  [NB*CC2*KVD];
__device__ __align__(128) __half g_ctx [NB*NTOK*CC2];
__device__ __align__(128) float  g_res [NB*NTOK*CC2];
__device__ __align__(128) __half g_x2  [NB*NTOK*CC2];
__device__ __align__(128) __half g_h1  [NB*NTOK*CC2*4];
__device__ __align__(128) __half g_WqT [NH*CC2*CC2];
__device__ __align__(128) __half g_WkT [NH*KVD*KVD];
__device__ __align__(128) __half g_WoutT[CC2*CC2];
__device__ __align__(128) __half g_fc1T[CC2*4*CC2];
__device__ __align__(128) __half g_fc2T[CC2*CC2*4];
__device__ __align__(128) __half g_Wvh [NH*KVD*KVD];
__device__ __align__(128) float  g_part[NPART*2];

// ---------------- helpers ----------------
__device__ __forceinline__ uint32_t smem_u32(const void* p) {
    uint32_t a;
    asm("{ .reg .u64 t; cvta.to.shared.u64 t, %1; cvt.u32.u64 %0, t; }" : "=r"(a) : "l"(p));
    return a;
}
#define CP_ASYNC16(sa, ga) \
    asm volatile("cp.async.cg.shared.global [%0], [%1], 16;" :: "r"(sa), "l"(ga) : "memory")
#define CP_COMMIT() asm volatile("cp.async.commit_group;" ::: "memory")
#define CP_WAIT3()  asm volatile("cp.async.wait_group 3;" ::: "memory")

#define LDSM_X4(r0, r1, r2, r3, addr) \
    asm volatile("ldmatrix.sync.aligned.m8n8.x4.shared.b16 {%0,%1,%2,%3}, [%4];" \
        : "=r"(r0), "=r"(r1), "=r"(r2), "=r"(r3) : "r"(addr))
#define LDSM_X4_T(r0, r1, r2, r3, addr) \
    asm volatile("ldmatrix.sync.aligned.m8n8.x4.trans.shared.b16 {%0,%1,%2,%3}, [%4];" \
        : "=r"(r0), "=r"(r1), "=r"(r2), "=r"(r3) : "r"(addr))

__device__ __forceinline__ void mma_f16(float* c, const uint32_t* a, const uint32_t* b) {
    asm volatile(
        "mma.sync.aligned.m16n8k16.row.col.f32.f16.f16.f32 "
        "{%0,%1,%2,%3}, {%4,%5,%6,%7}, {%8,%9}, {%0,%1,%2,%3};"
        : "+f"(c[0]), "+f"(c[1]), "+f"(c[2]), "+f"(c[3])
        : "r"(a[0]), "r"(a[1]), "r"(a[2]), "r"(a[3]), "r"(b[0]), "r"(b[1]));
}

// ---------------- fp16 NT GEMM (R14 winner): D = alpha*sum_seg A[M,K]@B[N,K]^T
#define BM 128
#define PADH 40
#define SM_BUF_H (128*PADH)
#define NSTAGE 4
#define SM_TOTAL_H (NSTAGE*2*SM_BUF_H*2)   // 81920 bytes

struct TCP {
    const void *A, *B; void *C;
    int lda, ldb, ldc, K;
    long sA, sB, sC;
    int aSel, bSel, nseg;
    long segA, segB;
    float alpha;
    const float* bias;
    const float* add; int ldAdd; long sAdd;
    float* part;
};

// EPI: 0 plain; 1 bias+gelu; 2 (+bias)+add; 3 plain + IN partial stats
// OUTH: 1 = half2 store, 0 = float2 store
template <int EPI, int OUTH>
__global__ void __launch_bounds__(128, 2) gemm_mma(TCP p)
{
    extern __shared__ float smf[];
    __half* sm = (__half*)smf;
    uint32_t sb = smem_u32(sm);

    int t = threadIdx.x, lane = t & 31, w = t >> 5;
    int z = blockIdx.z;
    int m0 = blockIdx.y * BM, n0 = blockIdx.x * 128;
    int az = p.aSel == 0 ? z : (p.aSel == 1 ? (z & 3) : (z >> 2));
    int bz = p.bSel == 0 ? z : (p.bSel == 1 ? (z & 3) : (z >> 2));
    const __half* Ab = (const __half*)p.A + (long)az * p.sA + (size_t)m0 * p.lda;
    const __half* Bb = (const __half*)p.B + (long)bz * p.sB + (size_t)n0 * p.ldb;

    int kIters = p.K >> 5;
    int nIt = kIters * p.nseg;
    int seg = 0, kk = 0;

    auto issue = [&](int buf) {
        const __half* Ag = Ab + (long)seg * p.segA + kk;
        const __half* Bg = Bb + (long)seg * p.segB + kk;
        uint32_t da = sb + (2 * buf) * SM_BUF_H * 2;
        uint32_t db = sb + (2 * buf + 1) * SM_BUF_H * 2;
        #pragma unroll
        for (int i = 0; i < 4; i++) {
            int task = t + i * 128, row = task >> 2, q = task & 3;
            CP_ASYNC16(da + row * (PADH * 2) + q * 16, Ag + (size_t)row * p.lda + q * 8);
            CP_ASYNC16(db + row * (PADH * 2) + q * 16, Bg + (size_t)row * p.ldb + q * 8);
        }
        CP_COMMIT();
        kk += 32; if (kk == p.K) { kk = 0; seg++; }
    };

    issue(0);
    if (nIt > 1) issue(1);
    if (nIt > 2) issue(2);

    int wm = (w >> 1) * 64, wn = (w & 1) * 64;
    float acc[4][8][4] = {};

    int rA  = (lane & 7) + ((lane >> 3) & 1) * 8;
    int kcA = (lane >> 4) * 8;
    int rB  = (lane & 7) + ((lane >> 4) & 1) * 8;
    int kcB = ((lane >> 3) & 1) * 8;
    uint32_t aoff[4], boff[4];
    #pragma unroll
    for (int mi = 0; mi < 4; mi++)
        aoff[mi] = ((wm + mi * 16 + rA) * PADH + kcA) * 2;
    #pragma unroll
    for (int np = 0; np < 4; np++)
        boff[np] = ((wn + np * 16 + rB) * PADH + kcB) * 2;

    for (int it = 0; it < nIt; it++) {
        int buf = it % NSTAGE;
        if (it + 3 < nIt) issue((it + 3) % NSTAGE);
        else CP_COMMIT();
        CP_WAIT3();
        __syncthreads();

        uint32_t da = sb + (2 * buf) * SM_BUF_H * 2;
        uint32_t db = sb + (2 * buf + 1) * SM_BUF_H * 2;
        #pragma unroll
        for (int ks = 0; ks < 2; ks++) {
            uint32_t a[4][4], b[8][2];
            #pragma unroll
            for (int mi = 0; mi < 4; mi++)
                LDSM_X4(a[mi][0], a[mi][1], a[mi][2], a[mi][3], da + aoff[mi] + ks * 32);
            #pragma unroll
            for (int np = 0; np < 4; np++)
                LDSM_X4(b[2*np][0], b[2*np][1], b[2*np+1][0], b[2*np+1][1],
                        db + boff[np] + ks * 32);
            #pragma unroll
            for (int mi = 0; mi < 4; mi++)
                #pragma unroll
                for (int ni = 0; ni < 8; ni++)
                    mma_f16(acc[mi][ni], a[mi], b[ni]);
        }
        __syncthreads();
    }

    // -------- epilogue --------
    float psum = 0.f, psq = 0.f;
    #pragma unroll
    for (int mi = 0; mi < 4; mi++) {
        #pragma unroll
        for (int ni = 0; ni < 8; ni++) {
            int r0 = m0 + wm + mi * 16 + (lane >> 2);
            int cc = n0 + wn + ni * 8 + (lane & 3) * 2;
            #pragma unroll
            for (int h = 0; h < 2; h++) {
                int gr = r0 + h * 8;
                float v0 = p.alpha * acc[mi][ni][h * 2 + 0];
                float v1 = p.alpha * acc[mi][ni][h * 2 + 1];
                if (EPI == 1) {
                    v0 += p.bias[cc]; v1 += p.bias[cc + 1];
                    v0 = 0.5f * v0 * (1.f + erff(v0 * 0.70710678118654752f));
                    v1 = 0.5f * v1 * (1.f + erff(v1 * 0.70710678118654752f));
                }
                if (EPI == 2) {
                    if (p.bias) { v0 += p.bias[cc]; v1 += p.bias[cc + 1]; }
                    const float* ap = p.add + (long)z * p.sAdd + (size_t)gr * p.ldAdd + cc;
                    float2 av = *(const float2*)ap;
                    v0 += av.x; v1 += av.y;
                }
                if (EPI == 3) { psum += v0 + v1; psq += v0 * v0 + v1 * v1; }
                if (OUTH) {
                    __half* Cz = (__half*)p.C + (long)z * p.sC;
                    *(__half2*)&Cz[(size_t)gr * p.ldc + cc] = __floats2half2_rn(v0, v1);
                } else {
                    float* Cz = (float*)p.C + (long)z * p.sC;
                    *(float2*)&Cz[(size_t)gr * p.ldc + cc] = make_float2(v0, v1);
                }
            }
        }
    }
    if (EPI == 3) {
        #pragma unroll
        for (int o = 16; o > 0; o >>= 1) {
            psum += __shfl_down_sync(0xffffffffu, psum, o);
            psq  += __shfl_down_sync(0xffffffffu, psq,  o);
        }
        __syncthreads();
        if (lane == 0) { smf[w] = psum; smf[8 + w] = psq; }
        __syncthreads();
        if (t == 0) {
            float s = 0.f, ss = 0.f;
            #pragma unroll
            for (int i = 0; i < 4; i++) { s += smf[i]; ss += smf[8 + i]; }
            int idx = (z * 4 + blockIdx.y) * gridDim.x + blockIdx.x;
            p.part[idx * 2] = s;
            p.part[idx * 2 + 1] = ss;
        }
    }
}

// ---------------- fp16 TN GEMM: D[M,N] = sum_k A[k,m] B[k,n], half out ------
// smem [k=32][m/n=128] with PADT=136 halves/row; fragments via ldmatrix.trans.
#define PADT 136
#define SM_BUF_T (32*PADT)                    // 4352 halves
#define SM_TOTAL_T (NSTAGE*2*SM_BUF_T*2)      // 69632 bytes

__global__ void __launch_bounds__(128, 2) gemm_mma_tn(TCP p)
{
    extern __shared__ float smf[];
    __half* sm = (__half*)smf;
    uint32_t sb = smem_u32(sm);

    int t = threadIdx.x, lane = t & 31, w = t >> 5;
    int z = blockIdx.z;
    int m0 = blockIdx.y * BM, n0 = blockIdx.x * 128;
    const __half* Ab = (const __half*)p.A + (long)z * p.sA + m0;
    const __half* Bb = (const __half*)p.B + (long)z * p.sB + n0;
    __half* Cz = (__half*)p.C + (long)z * p.sC;

    int nIt = p.K >> 5;
    int kk = 0;

    auto issue = [&](int buf) {
        const __half* Ag = Ab + (size_t)kk * p.lda;
        const __half* Bg = Bb + (size_t)kk * p.ldb;
        uint32_t da = sb + (2 * buf) * SM_BUF_T * 2;
        uint32_t db = sb + (2 * buf + 1) * SM_BUF_T * 2;
        #pragma unroll
        for (int i = 0; i < 4; i++) {
            int task = t + i * 128, row = task >> 4, q = task & 15;
            CP_ASYNC16(da + row * (PADT * 2) + q * 16, Ag + (size_t)row * p.lda + q * 8);
            CP_ASYNC16(db + row * (PADT * 2) + q * 16, Bg + (size_t)row * p.ldb + q * 8);
        }
        CP_COMMIT();
        kk += 32;
    };

    issue(0);
    if (nIt > 1) issue(1);
    if (nIt > 2) issue(2);

    int wm = (w >> 1) * 64, wn = (w & 1) * 64;
    float acc[4][8][4] = {};

    // .trans lane addressing: A wants (k=(lane&7)+((lane>>4)&1)*8, m=((lane>>3)&1)*8)
    int kA = (lane & 7) + ((lane >> 4) & 1) * 8;
    int mA = ((lane >> 3) & 1) * 8;
    int kB = (lane & 7) + ((lane >> 3) & 1) * 8;
    int nB = ((lane >> 4) & 1) * 8;
    uint32_t aoff[4], boff[4];
    #pragma unroll
    for (int mi = 0; mi < 4; mi++)
        aoff[mi] = (kA * PADT + wm + mi * 16 + mA) * 2;
    #pragma unroll
    for (int np = 0; np < 4; np++)
        boff[np] = (kB * PADT + wn + np * 16 + nB) * 2;

    for (int it = 0; it < nIt; it++) {
        int buf = it % NSTAGE;
        if (it + 3 < nIt) issue((it + 3) % NSTAGE);
        else CP_COMMIT();
        CP_WAIT3();
        __syncthreads();

        uint32_t da = sb + (2 * buf) * SM_BUF_T * 2;
        uint32_t db = sb + (2 * buf + 1) * SM_BUF_T * 2;
        #pragma unroll
        for (int ks = 0; ks < 2; ks++) {
            uint32_t koff = ks * 16 * PADT * 2;
            uint32_t a[4][4], b[8][2];
            #pragma unroll
            for (int mi = 0; mi < 4; mi++)
                LDSM_X4_T(a[mi][0], a[mi][1], a[mi][2], a[mi][3], da + aoff[mi] + koff);
            #pragma unroll
            for (int np = 0; np < 4; np++)
                LDSM_X4_T(b[2*np][0], b[2*np][1], b[2*np+1][0], b[2*np+1][1],
                          db + boff[np] + koff);
            #pragma unroll
            for (int mi = 0; mi < 4; mi++)
                #pragma unroll
                for (int ni = 0; ni < 8; ni++)
                    mma_f16(acc[mi][ni], a[mi], b[ni]);
        }
        __syncthreads();
    }

    #pragma unroll
    for (int mi = 0; mi < 4; mi++) {
        #pragma unroll
        for (int ni = 0; ni < 8; ni++) {
            int r0 = m0 + wm + mi * 16 + (lane >> 2);
            int cc = n0 + wn + ni * 8 + (lane & 3) * 2;
            #pragma unroll
            for (int h = 0; h < 2; h++) {
                int gr = r0 + h * 8;
                *(__half2*)&Cz[(size_t)gr * p.ldc + cc] =
                    __floats2half2_rn(acc[mi][ni][h * 2 + 0], acc[mi][ni][h * 2 + 1]);
            }
        }
    }
}

// ---------------- transpose fp32 -> half ----------------
__global__ void __launch_bounds__(256) transpose_h_kernel(
    const float* __restrict__ in, __half* __restrict__ out, int rows, int cols)
{
    __shared__ float tile[32][33];
    long zo = (long)blockIdx.z * rows * cols;
    const float* ip = in + zo;
    __half* op = out + zo;
    int c0 = blockIdx.x * 32, r0 = blockIdx.y * 32;
    int tx = threadIdx.x & 31, ty = threadIdx.x >> 5;
    #pragma unroll
    for (int i = 0; i < 4; i++)
        tile[ty + i * 8][tx] = ip[(size_t)(r0 + ty + i * 8) * cols + c0 + tx];
    __syncthreads();
    #pragma unroll
    for (int i = 0; i < 4; i++)
        op[(size_t)(c0 + ty + i * 8) * rows + r0 + tx] = __float2half(tile[tx][ty + i * 8]);
}

// ---------------- fp32 -> half convert (Wv) ----------------
__global__ void __launch_bounds__(256) f2h_kernel(const float4* __restrict__ in,
                                                  __half2* __restrict__ out, int n4)
{
    int i = blockIdx.x * 256 + threadIdx.x;
    if (i < n4) {
        float4 v = in[i];
        out[2 * i]     = __floats2half2_rn(v.x, v.y);
        out[2 * i + 1] = __floats2half2_rn(v.z, v.w);
    }
}

// ---------------- reductions ----------------
template <int NW>
__device__ __forceinline__ float bRSum(float v, float* sbuf) {
    #pragma unroll
    for (int o = 16; o > 0; o >>= 1) v += __shfl_down_sync(0xffffffffu, v, o);
    int lane = threadIdx.x & 31, w = threadIdx.x >> 5;
    if (lane == 0) sbuf[w] = v;
    __syncthreads();
    float tot = 0.f;
    #pragma unroll
    for (int i = 0; i < NW; i++) tot += sbuf[i];
    __syncthreads();
    return tot;
}
template <int NW>
__device__ __forceinline__ float bRMax(float v, float* sbuf) {
    #pragma unroll
    for (int o = 16; o > 0; o >>= 1) v = fmaxf(v, __shfl_xor_sync(0xffffffffu, v, o));
    int lane = threadIdx.x & 31, w = threadIdx.x >> 5;
    if (lane == 0) sbuf[w] = v;
    __syncthreads();
    float tot = -1e30f;
    #pragma unroll
    for (int i = 0; i < NW; i++) tot = fmaxf(tot, sbuf[i]);
    __syncthreads();
    return tot;
}

// ---------------- LN kernels ----------------
__global__ void __launch_bounds__(256) ln_all_kernel(
    const float* __restrict__ e1, const float* __restrict__ e2, const float* __restrict__ e3,
    const float* __restrict__ g1, const float* __restrict__ b1,
    const float* __restrict__ ga, const float* __restrict__ ba,
    __half* __restrict__ Xh, __half* __restrict__ c2h)
{
    __shared__ float xs[KVD];
    __shared__ float red[8];
    int tok = blockIdx.x, t = threadIdx.x;
    const float* p1 = e1 + (size_t)tok * 256;
    const float* p2 = e2 + (size_t)tok * 512;
    const float* p3 = e3 + (size_t)tok * 1024;
    xs[t] = p1[t];
    xs[256 + t] = p2[t];
    xs[512 + t] = p2[256 + t];
    #pragma unroll
    for (int i = 0; i < 4; i++) xs[768 + t + i * 256] = p3[t + i * 256];
    __syncthreads();
    float s = 0.f, ss = 0.f, s2 = 0.f, ss2 = 0.f;
    for (int i = t; i < KVD; i += 256) { float x = xs[i]; s += x; ss += x * x; }
    for (int i = t; i < 512; i += 256) { float x = xs[256 + i]; s2 += x; ss2 += x * x; }
    s  = bRSum<8>(s,  red);
    ss = bRSum<8>(ss, red);
    s2 = bRSum<8>(s2, red);
    ss2= bRSum<8>(ss2,red);
    float m  = s * (1.f / KVD), r = rsqrtf(ss * (1.f / KVD) - m * m + 1e-6f);
    float m2 = s2 * (1.f / 512.f), r2 = rsqrtf(ss2 * (1.f / 512.f) - m2 * m2 + 1e-6f);
    __half* Xho = Xh + (size_t)tok * KVD;
    __half* co = c2h + (size_t)tok * 512;
    for (int i = t; i < KVD; i += 256)
        Xho[i] = __float2half((xs[i] - m) * r * ga[i] + ba[i]);
    for (int i = t; i < 512; i += 256)
        co[i] = __float2half((xs[256 + i] - m2) * r2 * g1[i] + b1[i]);
}

__global__ void __launch_bounds__(256) ln512_kernel(
    const float* __restrict__ in, const float* __restrict__ g, const float* __restrict__ b,
    __half* __restrict__ out)
{
    __shared__ float red[8];
    int tok = blockIdx.x, t = threadIdx.x;
    const float* p = in + (size_t)tok * 512;
    float x0 = p[t], x1 = p[t + 256];
    float s = bRSum<8>(x0 + x1, red);
    float ss = bRSum<8>(x0 * x0 + x1 * x1, red);
    float m = s * (1.f / 512.f);
    float r = rsqrtf(ss * (1.f / 512.f) - m * m + 1e-6f);
    __half* o = out + (size_t)tok * 512;
    o[t] = __float2half((x0 - m) * r * g[t] + b[t]);
    o[t + 256] = __float2half((x1 - m) * r * g[t + 256] + b[t + 256]);
}

// ---------------- softmax over KV (half2) ----------------
__global__ void __launch_bounds__(128) softmax_kernel(__half2* __restrict__ S2,
                                                      const float* __restrict__ part)
{
    __shared__ float red[4];
    int row = blockIdx.x, t = threadIdx.x;
    int map = row >> 9;
    float s0 = 0.f, q0 = 0.f;
    const float2* pp = (const float2*)part + map * NTILEMAP;
    #pragma unroll 8
    for (int i = 0; i < NTILEMAP; i++) { float2 v = pp[i]; s0 += v.x; q0 += v.y; }
    float invn = 1.f / (float)MAPELEMS;
    float mean = s0 * invn;
    float r = rsqrtf(q0 * invn - mean * mean + 1e-5f);

    __half2* p = S2 + (size_t)row * (KVD / 2);
    float vx[7], vy[7];
    float mx = -1e30f;
    #pragma unroll
    for (int j = 0; j < 7; j++) {
        float2 f = __half22float2(p[t + j * 128]);
        vx[j] = f.x * r; vy[j] = f.y * r;
        mx = fmaxf(mx, fmaxf(vx[j], vy[j]));
    }
    mx = bRMax<4>(mx, red);
    float s = 0.f;
    #pragma unroll
    for (int j = 0; j < 7; j++) {
        vx[j] = expf(vx[j] - mx); vy[j] = expf(vy[j] - mx);
        s += vx[j] + vy[j];
    }
    s = bRSum<4>(s, red);
    float inv = 1.f / s;
    #pragma unroll
    for (int j = 0; j < 7; j++)
        p[t + j * 128] = __floats2half2_rn(vx[j] * inv, vy[j] * inv);
}

// ---------------- host ----------------
static inline TCP mkP(const void* A, const void* B, void* C,
                      int lda, int ldb, int ldc, int K,
                      long sA, long sB, long sC, int aSel, int bSel,
                      int nseg, long segA, long segB, float alpha,
                      const float* bias, const float* add, int ldAdd, long sAdd,
                      float* part = nullptr)
{
    TCP p; p.A = A; p.B = B; p.C = C; p.lda = lda; p.ldb = ldb; p.ldc = ldc; p.K = K;
    p.sA = sA; p.sB = sB; p.sC = sC; p.aSel = aSel; p.bSel = bSel;
    p.nseg = nseg; p.segA = segA; p.segB = segB; p.alpha = alpha;
    p.bias = bias; p.add = add; p.ldAdd = ldAdd; p.sAdd = sAdd; p.part = part;
    return p;
}

extern "C" void kernel_launch(void* const* d_in, const int* in_sizes, int n_in,
                              void* d_out, int out_size)
{
    const float* emb1   = (const float*)d_in[0];
    const float* emb2   = (const float*)d_in[1];
    const float* emb3   = (const float*)d_in[2];
    const float* Wq     = (const float*)d_in[3];
    const float* Wk     = (const float*)d_in[4];
    const float* Wv     = (const float*)d_in[5];
    const float* Wout   = (const float*)d_in[6];
    const float* ln1_g  = (const float*)d_in[7];
    const float* ln1_b  = (const float*)d_in[8];
    const float* lnall_g= (const float*)d_in[9];
    const float* lnall_b= (const float*)d_in[10];
    const float* lnffn_g= (const float*)d_in[11];
    const float* lnffn_b= (const float*)d_in[12];
    const float* fc1_w  = (const float*)d_in[13];
    const float* fc1_b  = (const float*)d_in[14];
    const float* fc2_w  = (const float*)d_in[15];
    const float* fc2_b  = (const float*)d_in[16];
    float* out = (float*)d_out;

    cudaFuncSetAttribute(gemm_mma<0,1>, cudaFuncAttributeMaxDynamicSharedMemorySize, SM_TOTAL_H);
    cudaFuncSetAttribute(gemm_mma<1,1>, cudaFuncAttributeMaxDynamicSharedMemorySize, SM_TOTAL_H);
    cudaFuncSetAttribute(gemm_mma<2,0>, cudaFuncAttributeMaxDynamicSharedMemorySize, SM_TOTAL_H);
    cudaFuncSetAttribute(gemm_mma<3,1>, cudaFuncAttributeMaxDynamicSharedMemorySize, SM_TOTAL_H);
    cudaFuncSetAttribute(gemm_mma_tn, cudaFuncAttributeMaxDynamicSharedMemorySize, SM_TOTAL_T);

    float *res, *part;
    __half *Xh, *c2h, *Gt, *T, *S, *Mt, *ctx, *x2, *h1, *WqT, *WkT, *WoutT, *fc1T, *fc2T, *Wvh;
    cudaGetSymbolAddress((void**)&Xh,   g_Xh);
    cudaGetSymbolAddress((void**)&c2h,  g_c2h);
    cudaGetSymbolAddress((void**)&Gt,   g_Gt);
    cudaGetSymbolAddress((void**)&T,    g_T);
    cudaGetSymbolAddress((void**)&S,    g_S);
    cudaGetSymbolAddress((void**)&Mt,   g_Mt);
    cudaGetSymbolAddress((void**)&ctx,  g_ctx);
    cudaGetSymbolAddress((void**)&res,  g_res);
    cudaGetSymbolAddress((void**)&x2,   g_x2);
    cudaGetSymbolAddress((void**)&h1,   g_h1);
    cudaGetSymbolAddress((void**)&WqT,  g_WqT);
    cudaGetSymbolAddress((void**)&WkT,  g_WkT);
    cudaGetSymbolAddress((void**)&WoutT,g_WoutT);
    cudaGetSymbolAddress((void**)&fc1T, g_fc1T);
    cudaGetSymbolAddress((void**)&fc2T, g_fc2T);
    cudaGetSymbolAddress((void**)&Wvh,  g_Wvh);
    cudaGetSymbolAddress((void**)&part, g_part);

    const long MAPSZ = (long)CC2 * KVD;
    const float inv_sqrt_kv = 1.f / sqrtf((float)KVD);

    // weight transposes (fp32 -> half) + Wv convert
    transpose_h_kernel<<<dim3(16,16,4), 256>>>(Wq, WqT, 512, 512);
    transpose_h_kernel<<<dim3(56,56,4), 256>>>(Wk, WkT, KVD, KVD);
    transpose_h_kernel<<<dim3(16,16,1), 256>>>(Wout, WoutT, 512, 512);
    transpose_h_kernel<<<dim3(64,16,1), 256>>>(fc1_w, fc1T, 512, 2048);
    transpose_h_kernel<<<dim3(16,64,1), 256>>>(fc2_w, fc2T, 2048, 512);
    f2h_kernel<<<(NH*KVD*KVD/4 + 255)/256, 256>>>((const float4*)Wv, (__half2*)Wvh,
                                                  NH*KVD*KVD/4);

    // 1. LayerNorms (half outputs only)
    ln_all_kernel<<<NB*NTOK, 256>>>(emb1, emb2, emb3, ln1_g, ln1_b,
                                    lnall_g, lnall_b, Xh, c2h);

    // 2. Gt[b][j][c] : TN fp16, M=KVD, N=512, K=1024, half out
    gemm_mma_tn<<<dim3(4,14,8), 128, SM_TOTAL_T>>>(
        mkP(Xh, c2h, Gt, KVD, 512, 512, NTOK,
            (long)NTOK*KVD, (long)NTOK*512, (long)KVD*512, 0, 0,
            1, 0, 0, 1.f, nullptr, nullptr, 0, 0));

    // 3. T[z][d][j] : M=512, N=KVD, K=512 (fp16)
    gemm_mma<0,1><<<dim3(14,4,32), 128, SM_TOTAL_H>>>(
        mkP(WqT, Gt, T, 512, 512, KVD, 512,
            (long)512*512, (long)KVD*512, MAPSZ, 1, 2,
            1, 0, 0, 1.f, nullptr, nullptr, 0, 0));

    // 4. S[z][d][k'] : M=512, N=KVD, K=KVD (fp16) + fused IN partial stats
    gemm_mma<3,1><<<dim3(14,4,32), 128, SM_TOTAL_H>>>(
        mkP(T, WkT, S, KVD, KVD, KVD, KVD,
            MAPSZ, (long)KVD*KVD, MAPSZ, 0, 1,
            1, 0, 0, inv_sqrt_kv, nullptr, nullptr, 0, 0, part));

    // 5. probs = softmax(rstd * S), half2 in place
    softmax_kernel<<<NMAPS*512, 128>>>((__half2*)S, part);

    // 6. Mt[b][c][j] : M=512, N=KVD, 4 segs over h (fp16)
    gemm_mma<0,1><<<dim3(14,4,8), 128, SM_TOTAL_H>>>(
        mkP(S, Wvh, Mt, KVD, KVD, KVD, KVD,
            4*MAPSZ, 0, (long)512*KVD, 0, 0,
            4, MAPSZ, (long)KVD*KVD, 0.25f, nullptr, nullptr, 0, 0));

    // 7. ctx[b][t][c] : M=1024, N=512, K=KVD (fp16)
    gemm_mma<0,1><<<dim3(4,8,8), 128, SM_TOTAL_H>>>(
        mkP(Xh, Mt, ctx, KVD, KVD, 512, KVD,
            (long)NTOK*KVD, (long)512*KVD, (long)NTOK*512, 0, 0,
            1, 0, 0, 1.f, nullptr, nullptr, 0, 0));

    // 8. res = ctx @ Wout + emb2 : M=8192, N=512, K=512 (fp16 in, fp32 out)
    gemm_mma<2,0><<<dim3(4,64,1), 128, SM_TOTAL_H>>>(
        mkP(ctx, WoutT, res, 512, 512, 512, 512,
            0, 0, 0, 0, 0, 1, 0, 0, 1.f, nullptr, emb2, 512, 0));

    // 9. x2 = LN(res), half out
    ln512_kernel<<<NB*NTOK, 256>>>(res, lnffn_g, lnffn_b, x2);

    // 10. h1 = gelu(x2 @ fc1 + b1) : M=8192, N=2048, K=512 (fp16)
    gemm_mma<1,1><<<dim3(16,64,1), 128, SM_TOTAL_H>>>(
        mkP(x2, fc1T, h1, 512, 512, 2048, 512,
            0, 0, 0, 0, 0, 1, 0, 0, 1.f, fc1_b, nullptr, 0, 0));

    // 11. out = h1 @ fc2 + b2 + res : M=8192, N=512, K=2048 (fp16 in, fp32 out)
    gemm_mma<2,0><<<dim3(4,64,1), 128, SM_TOTAL_H>>>(
        mkP(h1, fc2T, out, 2048, 2048, 512, 2048,
            0, 0, 0, 0, 0, 1, 0, 0, 1.f, fc2_b, res, 512, 0));
}